// round 3
// baseline (speedup 1.0000x reference)
#include <cuda_runtime.h>
#include <math.h>

#define B_   8
#define T_   1024
#define C_   768
#define H_   12
#define D_   64
#define C3_  2304

__device__ float g_qkv[(size_t)B_ * T_ * C3_];   // [B,T,3C]
__device__ float g_att[(size_t)B_ * T_ * C_];    // [B,T,C]

// ---------------------------------------------------------------------------
__device__ __forceinline__ unsigned f2tf32(float x) {
    unsigned u;
    asm("cvt.rna.tf32.f32 %0, %1;" : "=r"(u) : "f"(x));
    return u;
}

__device__ __forceinline__ void mma_tf32(float c[4],
    unsigned a0, unsigned a1, unsigned a2, unsigned a3,
    unsigned b0, unsigned b1)
{
    asm volatile(
        "mma.sync.aligned.m16n8k8.row.col.f32.tf32.tf32.f32 "
        "{%0,%1,%2,%3}, {%4,%5,%6,%7}, {%8,%9}, {%0,%1,%2,%3};\n"
        : "+f"(c[0]), "+f"(c[1]), "+f"(c[2]), "+f"(c[3])
        : "r"(a0), "r"(a1), "r"(a2), "r"(a3), "r"(b0), "r"(b1));
}

// ---------------------------------------------------------------------------
// TF32 GEMM with fragment-packed smem. 128x128 tile, BK=16, 8 warps (2x4),
// warp tile 64x32. A frags: LDS.128; B frags: LDS.64.
//
// A layout: [kb2][mt8][t4 4][g8][regslot4], regslot = (half+2*kh) ^ (kb<<1)
// B layout: [kb2][nt16][t4slot4][gslot8][reg2],
//           t4slot = t4 ^ (nt>>3), gslot = g ^ (nt&7)
// ---------------------------------------------------------------------------
__device__ __forceinline__ void storeA_frag(unsigned* buf, int r, int kb, int kh,
                                            float4 v) {
    int mt = r >> 4, g = r & 7;
    int rs = (((r >> 3) & 1) + 2 * kh) ^ (kb << 1);
    int base = (((kb * 8 + mt) * 4) * 8 + g) * 4 + rs;   // t4 stride = 32 words
    buf[base +  0] = f2tf32(v.x);
    buf[base + 32] = f2tf32(v.y);
    buf[base + 64] = f2tf32(v.z);
    buf[base + 96] = f2tf32(v.w);
}

__device__ __forceinline__ void storeB_frag(unsigned* buf, int k, int nt, int g0,
                                            float4 v) {
    int kb = k >> 3;
    int t4s = (k & 3) ^ ((nt >> 3) & 1);
    int reg = (k >> 2) & 1;
    int blk = ((kb * 16 + nt) * 4 + t4s) * 8;
    float f[4] = {v.x, v.y, v.z, v.w};
    #pragma unroll
    for (int i = 0; i < 4; i++)
        buf[(blk + ((g0 + i) ^ (nt & 7))) * 2 + reg] = f2tf32(f[i]);
}

__global__ __launch_bounds__(256) void gemm_tf32(
    const float* __restrict__ A, const float* __restrict__ W,
    const float* __restrict__ bias, float* __restrict__ Cout,
    int M, int N, int K)
{
    __shared__ __align__(16) unsigned As[2][2048];
    __shared__ __align__(16) unsigned Bs[2][2048];

    const int tid  = threadIdx.x;
    const int lane = tid & 31;
    const int wid  = tid >> 5;
    const int wm   = wid >> 2;           // 0..1
    const int wn   = wid & 3;            // 0..3
    const int g    = lane >> 2;          // 0..7
    const int t4   = lane & 3;           // 0..3
    const int t4x  = t4 ^ (wn >> 1);     // B t4-swizzle (uniform per warp)

    const int rowBase = blockIdx.y * 128;
    const int colBase = blockIdx.x * 128;

    float acc[4][4][4];
    #pragma unroll
    for (int i = 0; i < 4; i++)
        #pragma unroll
        for (int j = 0; j < 4; j++)
            #pragma unroll
            for (int q = 0; q < 4; q++) acc[i][j][q] = 0.f;

    // loader roles
    const int aR  = tid >> 1;            // A row 0..127
    const int aKb = tid & 1;             // which 8-k block
    const int bK  = tid >> 4;            // W k-row 0..15
    const int bNT = tid & 15;            // n-tile 0..15
    const int bC0 = bNT * 8;

    float4 av0, av1, bv0, bv1;
    av0 = *(const float4*)(A + (size_t)(rowBase + aR) * K + aKb * 8);
    av1 = *(const float4*)(A + (size_t)(rowBase + aR) * K + aKb * 8 + 4);
    bv0 = *(const float4*)(W + (size_t)bK * N + colBase + bC0);
    bv1 = *(const float4*)(W + (size_t)bK * N + colBase + bC0 + 4);
    storeA_frag(&As[0][0], aR, aKb, 0, av0);
    storeA_frag(&As[0][0], aR, aKb, 1, av1);
    storeB_frag(&Bs[0][0], bK, bNT, 0, bv0);
    storeB_frag(&Bs[0][0], bK, bNT, 4, bv1);
    __syncthreads();

    const int nstage = K / 16;
    for (int s = 0; s < nstage; s++) {
        const int buf = s & 1;
        if (s + 1 < nstage) {
            const int k0 = (s + 1) * 16;
            av0 = *(const float4*)(A + (size_t)(rowBase + aR) * K + k0 + aKb * 8);
            av1 = *(const float4*)(A + (size_t)(rowBase + aR) * K + k0 + aKb * 8 + 4);
            bv0 = *(const float4*)(W + (size_t)(k0 + bK) * N + colBase + bC0);
            bv1 = *(const float4*)(W + (size_t)(k0 + bK) * N + colBase + bC0 + 4);
        }

        const unsigned* a  = &As[buf][0];
        const unsigned* bb = &Bs[buf][0];
        #pragma unroll
        for (int kb = 0; kb < 2; kb++) {
            unsigned af[4][4];
            #pragma unroll
            for (int mt = 0; mt < 4; mt++) {
                int mtg = wm * 4 + mt;
                uint4 t = *(const uint4*)&a[(((kb * 8 + mtg) * 4 + t4) * 8 + g) * 4];
                if (kb == 0) { af[mt][0]=t.x; af[mt][1]=t.y; af[mt][2]=t.z; af[mt][3]=t.w; }
                else         { af[mt][0]=t.z; af[mt][1]=t.w; af[mt][2]=t.x; af[mt][3]=t.y; }
            }
            unsigned bf[4][2];
            #pragma unroll
            for (int nt = 0; nt < 4; nt++) {
                int ntg = wn * 4 + nt;
                uint2 t = *(const uint2*)&bb[(((kb * 16 + ntg) * 4 + t4x) * 8 +
                                              (g ^ (ntg & 7))) * 2];
                bf[nt][0] = t.x; bf[nt][1] = t.y;
            }
            #pragma unroll
            for (int mt = 0; mt < 4; mt++)
                #pragma unroll
                for (int nt = 0; nt < 4; nt++)
                    mma_tf32(acc[mt][nt], af[mt][0], af[mt][1], af[mt][2], af[mt][3],
                             bf[nt][0], bf[nt][1]);
        }

        if (s + 1 < nstage) {
            storeA_frag(&As[buf ^ 1][0], aR, aKb, 0, av0);
            storeA_frag(&As[buf ^ 1][0], aR, aKb, 1, av1);
            storeB_frag(&Bs[buf ^ 1][0], bK, bNT, 0, bv0);
            storeB_frag(&Bs[buf ^ 1][0], bK, bNT, 4, bv1);
        }
        __syncthreads();
    }

    // epilogue
    #pragma unroll
    for (int mt = 0; mt < 4; mt++) {
        #pragma unroll
        for (int nt = 0; nt < 4; nt++) {
            int r0 = rowBase + wm * 64 + mt * 16 + g;
            int c  = colBase + wn * 32 + nt * 8 + 2 * t4;
            float bx = bias[c], by = bias[c + 1];
            float2 v0 = make_float2(acc[mt][nt][0] + bx, acc[mt][nt][1] + by);
            float2 v1 = make_float2(acc[mt][nt][2] + bx, acc[mt][nt][3] + by);
            *(float2*)(Cout + (size_t)r0 * N + c)       = v0;
            *(float2*)(Cout + (size_t)(r0 + 8) * N + c) = v1;
        }
    }
}

// ---------------------------------------------------------------------------
// Flash causal attention, tf32 mma, fragment-packed K/V/P, Q in registers.
// 128 threads = 4 warps, 64 q-rows/block (16/warp), 32-key tiles.
// K layout: [kbd8][nt4][t4 4][gslot8][reg2], gslot = g ^ (kbd&7)
// V layout: [kbv4][nt8][t4 4][gslot8][reg2], gslot = g ^ (nt&7)
// P layout: [wid4][kbp4][t4 4][g8][reg4]
// ---------------------------------------------------------------------------
__global__ __launch_bounds__(128) void attn_tf32(
    const float* __restrict__ qkv, float* __restrict__ outp)
{
    __shared__ __align__(16) float    Qstage[64 * 68];
    __shared__ __align__(16) unsigned Kf[2048];
    __shared__ __align__(16) unsigned Vf[2048];
    __shared__ __align__(16) unsigned Pf[2048];

    const int tid  = threadIdx.x;
    const int lane = tid & 31;
    const int wid  = tid >> 5;
    const int g    = lane >> 2;
    const int t4   = lane & 3;

    const int bh = blockIdx.y;
    const int b  = bh / H_;
    const int h  = bh % H_;
    const int qt = blockIdx.x;
    const int qBase = qt * 64;

    const float* qptr = qkv + (size_t)b * T_ * C3_ + h * D_;
    const float* kptr = qptr + C_;
    const float* vptr = qptr + 2 * C_;

    // stage Q (plain layout), then pull fragments into registers
    #pragma unroll
    for (int l = 0; l < 8; l++) {
        int idx = tid + l * 128;
        int r = idx >> 4, c4 = (idx & 15) << 2;
        float4 v = *(const float4*)(qptr + (size_t)(qBase + r) * C3_ + c4);
        *(float4*)&Qstage[r * 68 + c4] = v;
    }
    __syncthreads();

    const int rowL = wid * 16 + g;
    unsigned qa[8][4];
    #pragma unroll
    for (int kbq = 0; kbq < 8; kbq++) {
        qa[kbq][0] = f2tf32(Qstage[(rowL    ) * 68 + kbq * 8 + t4]);
        qa[kbq][1] = f2tf32(Qstage[(rowL + 8) * 68 + kbq * 8 + t4]);
        qa[kbq][2] = f2tf32(Qstage[(rowL    ) * 68 + kbq * 8 + t4 + 4]);
        qa[kbq][3] = f2tf32(Qstage[(rowL + 8) * 68 + kbq * 8 + t4 + 4]);
    }

    float o[8][4];
    #pragma unroll
    for (int nt = 0; nt < 8; nt++)
        #pragma unroll
        for (int q = 0; q < 4; q++) o[nt][q] = 0.f;
    float m0 = -1e30f, m1 = -1e30f, l0 = 0.f, l1 = 0.f;

    const float scale = 0.125f;
    const int row0 = qBase + rowL;
    const int row1 = row0 + 8;

    const int ktmax = 2 * qt + 1;
    for (int kt = 0; kt <= ktmax; kt++) {
        const int kBase = kt * 32;
        const bool domask = (kt >= 2 * qt);

        __syncthreads();   // everyone done with previous Kf/Vf
        // load K,V tiles straight into fragment layout
        #pragma unroll
        for (int l = 0; l < 4; l++) {
            int idx = tid + l * 128;
            int r  = idx >> 4;               // 0..31
            int c4 = (idx & 15) << 2;        // 0..60
            float4 kv = *(const float4*)(kptr + (size_t)(kBase + r) * C3_ + c4);
            float4 vv = *(const float4*)(vptr + (size_t)(kBase + r) * C3_ + c4);
            {
                int nt = r >> 3, gk = r & 7;
                int kbd = c4 >> 3, reg = (c4 >> 2) & 1;
                int gs = gk ^ (kbd & 7);
                float f[4] = {kv.x, kv.y, kv.z, kv.w};
                #pragma unroll
                for (int i = 0; i < 4; i++)
                    Kf[(((kbd * 4 + nt) * 4 + i) * 8 + gs) * 2 + reg] = f2tf32(f[i]);
            }
            {
                int kbv = r >> 3, t4v = r & 3, regv = (r >> 2) & 1;
                int ntv = c4 >> 3, gv0 = c4 & 7;
                float f[4] = {vv.x, vv.y, vv.z, vv.w};
                #pragma unroll
                for (int i = 0; i < 4; i++)
                    Vf[(((kbv * 8 + ntv) * 4 + t4v) * 8 + ((gv0 + i) ^ (ntv & 7))) * 2
                       + regv] = f2tf32(f[i]);
            }
        }
        __syncthreads();

        // S = Q @ K^T
        float s[4][4];
        #pragma unroll
        for (int nt = 0; nt < 4; nt++)
            #pragma unroll
            for (int q = 0; q < 4; q++) s[nt][q] = 0.f;

        #pragma unroll
        for (int kbd = 0; kbd < 8; kbd++) {
            #pragma unroll
            for (int nt = 0; nt < 4; nt++) {
                uint2 bv = *(const uint2*)&Kf[(((kbd * 4 + nt) * 4 + t4) * 8 +
                                               (g ^ (kbd & 7))) * 2];
                mma_tf32(s[nt], qa[kbd][0], qa[kbd][1], qa[kbd][2], qa[kbd][3],
                         bv.x, bv.y);
            }
        }

        // scale + causal mask
        #pragma unroll
        for (int nt = 0; nt < 4; nt++) {
            #pragma unroll
            for (int q = 0; q < 4; q++) {
                s[nt][q] *= scale;
                if (domask) {
                    int col = kBase + nt * 8 + 2 * t4 + (q & 1);
                    int row = (q < 2) ? row0 : row1;
                    if (col > row) s[nt][q] = -1e30f;
                }
            }
        }

        // online softmax (rows row0,row1), reductions within 4-lane groups
        float mt0 = -1e30f, mt1 = -1e30f;
        #pragma unroll
        for (int nt = 0; nt < 4; nt++) {
            mt0 = fmaxf(mt0, fmaxf(s[nt][0], s[nt][1]));
            mt1 = fmaxf(mt1, fmaxf(s[nt][2], s[nt][3]));
        }
        mt0 = fmaxf(mt0, __shfl_xor_sync(0xffffffffu, mt0, 1));
        mt0 = fmaxf(mt0, __shfl_xor_sync(0xffffffffu, mt0, 2));
        mt1 = fmaxf(mt1, __shfl_xor_sync(0xffffffffu, mt1, 1));
        mt1 = fmaxf(mt1, __shfl_xor_sync(0xffffffffu, mt1, 2));

        float mn0 = fmaxf(m0, mt0), mn1 = fmaxf(m1, mt1);
        float al0 = __expf(m0 - mn0), al1 = __expf(m1 - mn1);
        m0 = mn0; m1 = mn1;

        float rs0 = 0.f, rs1 = 0.f;
        #pragma unroll
        for (int nt = 0; nt < 4; nt++) {
            s[nt][0] = __expf(s[nt][0] - mn0);
            s[nt][1] = __expf(s[nt][1] - mn0);
            s[nt][2] = __expf(s[nt][2] - mn1);
            s[nt][3] = __expf(s[nt][3] - mn1);
            rs0 += s[nt][0] + s[nt][1];
            rs1 += s[nt][2] + s[nt][3];
        }
        rs0 += __shfl_xor_sync(0xffffffffu, rs0, 1);
        rs0 += __shfl_xor_sync(0xffffffffu, rs0, 2);
        rs1 += __shfl_xor_sync(0xffffffffu, rs1, 1);
        rs1 += __shfl_xor_sync(0xffffffffu, rs1, 2);
        l0 = l0 * al0 + rs0;
        l1 = l1 * al1 + rs1;

        #pragma unroll
        for (int nt = 0; nt < 8; nt++) {
            o[nt][0] *= al0; o[nt][1] *= al0;
            o[nt][2] *= al1; o[nt][3] *= al1;
        }

        // stage P -> fragment layout (per-warp region)
        #pragma unroll
        for (int nt = 0; nt < 4; nt++) {
            #pragma unroll
            for (int q = 0; q < 4; q++) {
                int c8  = 2 * t4 + (q & 1);
                int t4p = c8 & 3;
                int reg = (q >> 1) + 2 * (c8 >> 2);
                Pf[(((wid * 4 + nt) * 4 + t4p) * 8 + g) * 4 + reg] = f2tf32(s[nt][q]);
            }
        }
        __syncwarp();

        // O += P @ V
        #pragma unroll
        for (int kbp = 0; kbp < 4; kbp++) {
            uint4 pa = *(const uint4*)&Pf[(((wid * 4 + kbp) * 4 + t4) * 8 + g) * 4];
            #pragma unroll
            for (int nt = 0; nt < 8; nt++) {
                uint2 bv = *(const uint2*)&Vf[(((kbp * 8 + nt) * 4 + t4) * 8 +
                                               (g ^ (nt & 7))) * 2];
                mma_tf32(o[nt], pa.x, pa.y, pa.z, pa.w, bv.x, bv.y);
            }
        }
    }

    // epilogue
    float inv0 = 1.f / l0, inv1 = 1.f / l1;
    #pragma unroll
    for (int nt = 0; nt < 8; nt++) {
        int d = nt * 8 + 2 * t4;
        float2 v0 = make_float2(o[nt][0] * inv0, o[nt][1] * inv0);
        float2 v1 = make_float2(o[nt][2] * inv1, o[nt][3] * inv1);
        *(float2*)(outp + ((size_t)b * T_ + row0) * C_ + h * D_ + d) = v0;
        *(float2*)(outp + ((size_t)b * T_ + row1) * C_ + h * D_ + d) = v1;
    }
}

// ---------------------------------------------------------------------------
extern "C" void kernel_launch(void* const* d_in, const int* in_sizes, int n_in,
                              void* d_out, int out_size)
{
    (void)in_sizes; (void)n_in; (void)out_size;
    const float* x      = (const float*)d_in[0];
    const float* w_attn = (const float*)d_in[1];
    const float* b_attn = (const float*)d_in[2];
    const float* w_proj = (const float*)d_in[3];
    const float* b_proj = (const float*)d_in[4];
    float* out = (float*)d_out;

    float *qkv = nullptr, *att = nullptr;
    cudaGetSymbolAddress((void**)&qkv, g_qkv);
    cudaGetSymbolAddress((void**)&att, g_att);

    gemm_tf32<<<dim3(C3_ / 128, (B_ * T_) / 128), 256>>>(
        x, w_attn, b_attn, qkv, B_ * T_, C3_, C_);

    attn_tf32<<<dim3(T_ / 64, B_ * H_), 128>>>(qkv, att);

    gemm_tf32<<<dim3(C_ / 128, (B_ * T_) / 128), 256>>>(
        att, w_proj, b_proj, out, B_ * T_, C_, C_);
}

// round 4
// speedup vs baseline: 1.4111x; 1.4111x over previous
#include <cuda_runtime.h>
#include <math.h>

#define B_   8
#define T_   1024
#define C_   768
#define H_   12
#define D_   64
#define C3_  2304

__device__ float g_qkv[(size_t)B_ * T_ * C3_];   // [B,T,3C]
__device__ float g_att[(size_t)B_ * T_ * C_];    // [B,T,C]

// ---------------------------------------------------------------------------
__device__ __forceinline__ unsigned f2tf32(float x) {
    unsigned u;
    asm("cvt.rna.tf32.f32 %0, %1;" : "=r"(u) : "f"(x));
    return u;
}

__device__ __forceinline__ uint4 f2tf32x4(float4 v) {
    uint4 u;
    u.x = f2tf32(v.x); u.y = f2tf32(v.y); u.z = f2tf32(v.z); u.w = f2tf32(v.w);
    return u;
}

__device__ __forceinline__ void mma_tf32(float c[4],
    unsigned a0, unsigned a1, unsigned a2, unsigned a3,
    unsigned b0, unsigned b1)
{
    asm volatile(
        "mma.sync.aligned.m16n8k8.row.col.f32.tf32.tf32.f32 "
        "{%0,%1,%2,%3}, {%4,%5,%6,%7}, {%8,%9}, {%0,%1,%2,%3};\n"
        : "+f"(c[0]), "+f"(c[1]), "+f"(c[2]), "+f"(c[3])
        : "r"(a0), "r"(a1), "r"(a2), "r"(a3), "r"(b0), "r"(b1));
}

// ---------------------------------------------------------------------------
// TF32 GEMM: Cout[M,N] = A[M,K] @ W[K,N] + bias
// 128x128 block tile, BK=16, 128 threads = 4 warps (2m x 2n),
// warp tile 64x64 (mt=4, nt=8). Padded smem, conflict-free fragment reads.
// ---------------------------------------------------------------------------
#define AST 20    // As row stride (16 k + 4 pad)
#define BST 136   // Bs row stride (128 n + 8 pad)

__global__ __launch_bounds__(128) void gemm_tf32(
    const float* __restrict__ A, const float* __restrict__ W,
    const float* __restrict__ bias, float* __restrict__ Cout,
    int M, int N, int K)
{
    __shared__ __align__(16) unsigned As[2][128 * AST];
    __shared__ __align__(16) unsigned Bs[2][16 * BST];

    const int tid  = threadIdx.x;
    const int lane = tid & 31;
    const int wid  = tid >> 5;
    const int wm   = wid >> 1;           // 0..1
    const int wn   = wid & 1;            // 0..1
    const int g    = lane >> 2;          // 0..7
    const int t4   = lane & 3;           // 0..3

    const int rowBase = blockIdx.y * 128;
    const int colBase = blockIdx.x * 128;

    float acc[4][8][4];
    #pragma unroll
    for (int i = 0; i < 4; i++)
        #pragma unroll
        for (int j = 0; j < 8; j++)
            #pragma unroll
            for (int q = 0; q < 4; q++) acc[i][j][q] = 0.f;

    // loader roles (128 threads)
    const int aR  = tid >> 1;            // A rows aR and aR+64
    const int aKb = (tid & 1) * 8;       // k sub-block 0 or 8
    const int bK  = tid >> 3;            // W k-row 0..15
    const int bC  = (tid & 7) * 16;      // 16 consecutive n per thread

    float4 av0, av1, av2, av3, bv0, bv1, bv2, bv3;
    av0 = *(const float4*)(A + (size_t)(rowBase + aR) * K + aKb);
    av1 = *(const float4*)(A + (size_t)(rowBase + aR) * K + aKb + 4);
    av2 = *(const float4*)(A + (size_t)(rowBase + aR + 64) * K + aKb);
    av3 = *(const float4*)(A + (size_t)(rowBase + aR + 64) * K + aKb + 4);
    bv0 = *(const float4*)(W + (size_t)bK * N + colBase + bC);
    bv1 = *(const float4*)(W + (size_t)bK * N + colBase + bC + 4);
    bv2 = *(const float4*)(W + (size_t)bK * N + colBase + bC + 8);
    bv3 = *(const float4*)(W + (size_t)bK * N + colBase + bC + 12);
    {
        *(uint4*)&As[0][aR * AST + aKb]            = f2tf32x4(av0);
        *(uint4*)&As[0][aR * AST + aKb + 4]        = f2tf32x4(av1);
        *(uint4*)&As[0][(aR + 64) * AST + aKb]     = f2tf32x4(av2);
        *(uint4*)&As[0][(aR + 64) * AST + aKb + 4] = f2tf32x4(av3);
        *(uint4*)&Bs[0][bK * BST + bC]      = f2tf32x4(bv0);
        *(uint4*)&Bs[0][bK * BST + bC + 4]  = f2tf32x4(bv1);
        *(uint4*)&Bs[0][bK * BST + bC + 8]  = f2tf32x4(bv2);
        *(uint4*)&Bs[0][bK * BST + bC + 12] = f2tf32x4(bv3);
    }
    __syncthreads();

    const int nstage = K / 16;
    for (int s = 0; s < nstage; s++) {
        const int buf = s & 1;
        if (s + 1 < nstage) {
            const int k0 = (s + 1) * 16;
            av0 = *(const float4*)(A + (size_t)(rowBase + aR) * K + k0 + aKb);
            av1 = *(const float4*)(A + (size_t)(rowBase + aR) * K + k0 + aKb + 4);
            av2 = *(const float4*)(A + (size_t)(rowBase + aR + 64) * K + k0 + aKb);
            av3 = *(const float4*)(A + (size_t)(rowBase + aR + 64) * K + k0 + aKb + 4);
            bv0 = *(const float4*)(W + (size_t)(k0 + bK) * N + colBase + bC);
            bv1 = *(const float4*)(W + (size_t)(k0 + bK) * N + colBase + bC + 4);
            bv2 = *(const float4*)(W + (size_t)(k0 + bK) * N + colBase + bC + 8);
            bv3 = *(const float4*)(W + (size_t)(k0 + bK) * N + colBase + bC + 12);
        }

        const unsigned* a  = &As[buf][0];
        const unsigned* bb = &Bs[buf][0];
        #pragma unroll
        for (int kb = 0; kb < 16; kb += 8) {
            unsigned af[4][4];
            #pragma unroll
            for (int mt = 0; mt < 4; mt++) {
                int r0 = wm * 64 + mt * 16 + g;
                af[mt][0] = a[(r0    ) * AST + kb + t4];
                af[mt][1] = a[(r0 + 8) * AST + kb + t4];
                af[mt][2] = a[(r0    ) * AST + kb + t4 + 4];
                af[mt][3] = a[(r0 + 8) * AST + kb + t4 + 4];
            }
            unsigned bf[8][2];
            #pragma unroll
            for (int nt = 0; nt < 8; nt++) {
                int c0 = wn * 64 + nt * 8 + g;
                bf[nt][0] = bb[(kb + t4    ) * BST + c0];
                bf[nt][1] = bb[(kb + t4 + 4) * BST + c0];
            }
            #pragma unroll
            for (int mt = 0; mt < 4; mt++)
                #pragma unroll
                for (int nt = 0; nt < 8; nt++)
                    mma_tf32(acc[mt][nt], af[mt][0], af[mt][1], af[mt][2], af[mt][3],
                             bf[nt][0], bf[nt][1]);
        }

        if (s + 1 < nstage) {
            unsigned* aw = &As[buf ^ 1][0];
            unsigned* bw = &Bs[buf ^ 1][0];
            *(uint4*)&aw[aR * AST + aKb]            = f2tf32x4(av0);
            *(uint4*)&aw[aR * AST + aKb + 4]        = f2tf32x4(av1);
            *(uint4*)&aw[(aR + 64) * AST + aKb]     = f2tf32x4(av2);
            *(uint4*)&aw[(aR + 64) * AST + aKb + 4] = f2tf32x4(av3);
            *(uint4*)&bw[bK * BST + bC]      = f2tf32x4(bv0);
            *(uint4*)&bw[bK * BST + bC + 4]  = f2tf32x4(bv1);
            *(uint4*)&bw[bK * BST + bC + 8]  = f2tf32x4(bv2);
            *(uint4*)&bw[bK * BST + bC + 12] = f2tf32x4(bv3);
        }
        __syncthreads();
    }

    // epilogue
    #pragma unroll
    for (int mt = 0; mt < 4; mt++) {
        #pragma unroll
        for (int nt = 0; nt < 8; nt++) {
            int r0 = rowBase + wm * 64 + mt * 16 + g;
            int c  = colBase + wn * 64 + nt * 8 + 2 * t4;
            float bx = bias[c], by = bias[c + 1];
            float2 v0 = make_float2(acc[mt][nt][0] + bx, acc[mt][nt][1] + by);
            float2 v1 = make_float2(acc[mt][nt][2] + bx, acc[mt][nt][3] + by);
            *(float2*)(Cout + (size_t)r0 * N + c)       = v0;
            *(float2*)(Cout + (size_t)(r0 + 8) * N + c) = v1;
        }
    }
}

// ---------------------------------------------------------------------------
// Flash causal attention, tf32 mma (R2 structure; Q fragments hoisted to regs).
// 128 threads = 4 warps; each warp owns 16 q-rows of a 64-row q tile;
// key tiles of 32.
// ---------------------------------------------------------------------------
#define QST 68
#define KST 68
#define VST 72
#define PST 36

__global__ __launch_bounds__(128) void attn_tf32(
    const float* __restrict__ qkv, float* __restrict__ outp)
{
    __shared__ unsigned Qs[64 * QST];
    __shared__ unsigned Ks[32 * KST];
    __shared__ unsigned Vs[32 * VST];
    __shared__ unsigned Ps[64 * PST];

    const int tid  = threadIdx.x;
    const int lane = tid & 31;
    const int wid  = tid >> 5;           // 0..3
    const int g    = lane >> 2;
    const int t4   = lane & 3;

    const int bh = blockIdx.y;
    const int b  = bh / H_;
    const int h  = bh % H_;
    const int qt = blockIdx.x;
    const int qBase = qt * 64;

    const float* qptr = qkv + (size_t)b * T_ * C3_ + h * D_;
    const float* kptr = qptr + C_;
    const float* vptr = qptr + 2 * C_;

    // load Q tile (64x64), tf32
    #pragma unroll
    for (int l = 0; l < 8; l++) {
        int idx = tid + l * 128;
        int r = idx >> 4, c4 = (idx & 15) << 2;
        float4 v = *(const float4*)(qptr + (size_t)(qBase + r) * C3_ + c4);
        Qs[r * QST + c4 + 0] = f2tf32(v.x);
        Qs[r * QST + c4 + 1] = f2tf32(v.y);
        Qs[r * QST + c4 + 2] = f2tf32(v.z);
        Qs[r * QST + c4 + 3] = f2tf32(v.w);
    }
    __syncthreads();

    const int rowL = wid * 16 + g;
    // hoist Q fragments into registers once (saves 32 LDS per key tile)
    unsigned qa[8][4];
    #pragma unroll
    for (int kbq = 0; kbq < 8; kbq++) {
        qa[kbq][0] = Qs[(rowL    ) * QST + kbq * 8 + t4];
        qa[kbq][1] = Qs[(rowL + 8) * QST + kbq * 8 + t4];
        qa[kbq][2] = Qs[(rowL    ) * QST + kbq * 8 + t4 + 4];
        qa[kbq][3] = Qs[(rowL + 8) * QST + kbq * 8 + t4 + 4];
    }

    float o[8][4];
    #pragma unroll
    for (int nt = 0; nt < 8; nt++)
        #pragma unroll
        for (int q = 0; q < 4; q++) o[nt][q] = 0.f;
    float m0 = -1e30f, m1 = -1e30f, l0 = 0.f, l1 = 0.f;

    const float scale = 0.125f;
    const int row0 = qBase + rowL;
    const int row1 = row0 + 8;

    const int ktmax = 2 * qt + 1;
    for (int kt = 0; kt <= ktmax; kt++) {
        const int kBase = kt * 32;
        const bool domask = (kt >= 2 * qt);

        __syncthreads();   // all warps done with previous Ks/Vs
        #pragma unroll
        for (int l = 0; l < 4; l++) {
            int idx = tid + l * 128;
            int r = idx >> 4, c4 = (idx & 15) << 2;
            float4 kv = *(const float4*)(kptr + (size_t)(kBase + r) * C3_ + c4);
            Ks[r * KST + c4 + 0] = f2tf32(kv.x);
            Ks[r * KST + c4 + 1] = f2tf32(kv.y);
            Ks[r * KST + c4 + 2] = f2tf32(kv.z);
            Ks[r * KST + c4 + 3] = f2tf32(kv.w);
            float4 vv = *(const float4*)(vptr + (size_t)(kBase + r) * C3_ + c4);
            Vs[r * VST + c4 + 0] = f2tf32(vv.x);
            Vs[r * VST + c4 + 1] = f2tf32(vv.y);
            Vs[r * VST + c4 + 2] = f2tf32(vv.z);
            Vs[r * VST + c4 + 3] = f2tf32(vv.w);
        }
        __syncthreads();

        // S = Q @ K^T : warp tile 16 x 32
        float s[4][4];
        #pragma unroll
        for (int nt = 0; nt < 4; nt++)
            #pragma unroll
            for (int q = 0; q < 4; q++) s[nt][q] = 0.f;

        #pragma unroll
        for (int kb8 = 0; kb8 < 8; kb8++) {
            #pragma unroll
            for (int nt = 0; nt < 4; nt++) {
                unsigned b0 = Ks[(nt * 8 + g) * KST + kb8 * 8 + t4];
                unsigned b1 = Ks[(nt * 8 + g) * KST + kb8 * 8 + t4 + 4];
                mma_tf32(s[nt], qa[kb8][0], qa[kb8][1], qa[kb8][2], qa[kb8][3],
                         b0, b1);
            }
        }

        // scale + causal mask
        #pragma unroll
        for (int nt = 0; nt < 4; nt++) {
            #pragma unroll
            for (int q = 0; q < 4; q++) {
                s[nt][q] *= scale;
                if (domask) {
                    int col = kBase + nt * 8 + 2 * t4 + (q & 1);
                    int row = (q < 2) ? row0 : row1;
                    if (col > row) s[nt][q] = -1e30f;
                }
            }
        }

        // online softmax (rows row0, row1) — reduce within 4-lane groups
        float mt0 = -1e30f, mt1 = -1e30f;
        #pragma unroll
        for (int nt = 0; nt < 4; nt++) {
            mt0 = fmaxf(mt0, fmaxf(s[nt][0], s[nt][1]));
            mt1 = fmaxf(mt1, fmaxf(s[nt][2], s[nt][3]));
        }
        mt0 = fmaxf(mt0, __shfl_xor_sync(0xffffffffu, mt0, 1));
        mt0 = fmaxf(mt0, __shfl_xor_sync(0xffffffffu, mt0, 2));
        mt1 = fmaxf(mt1, __shfl_xor_sync(0xffffffffu, mt1, 1));
        mt1 = fmaxf(mt1, __shfl_xor_sync(0xffffffffu, mt1, 2));

        float mn0 = fmaxf(m0, mt0), mn1 = fmaxf(m1, mt1);
        float al0 = __expf(m0 - mn0), al1 = __expf(m1 - mn1);
        m0 = mn0; m1 = mn1;

        float rs0 = 0.f, rs1 = 0.f;
        #pragma unroll
        for (int nt = 0; nt < 4; nt++) {
            s[nt][0] = __expf(s[nt][0] - mn0);
            s[nt][1] = __expf(s[nt][1] - mn0);
            s[nt][2] = __expf(s[nt][2] - mn1);
            s[nt][3] = __expf(s[nt][3] - mn1);
            rs0 += s[nt][0] + s[nt][1];
            rs1 += s[nt][2] + s[nt][3];
        }
        rs0 += __shfl_xor_sync(0xffffffffu, rs0, 1);
        rs0 += __shfl_xor_sync(0xffffffffu, rs0, 2);
        rs1 += __shfl_xor_sync(0xffffffffu, rs1, 1);
        rs1 += __shfl_xor_sync(0xffffffffu, rs1, 2);
        l0 = l0 * al0 + rs0;
        l1 = l1 * al1 + rs1;

        #pragma unroll
        for (int nt = 0; nt < 8; nt++) {
            o[nt][0] *= al0; o[nt][1] *= al0;
            o[nt][2] *= al1; o[nt][3] *= al1;
        }

        // stage P -> smem (tf32) for the PV mma
        #pragma unroll
        for (int nt = 0; nt < 4; nt++) {
            int c = nt * 8 + 2 * t4;
            uint2 p0 = make_uint2(f2tf32(s[nt][0]), f2tf32(s[nt][1]));
            uint2 p1 = make_uint2(f2tf32(s[nt][2]), f2tf32(s[nt][3]));
            *(uint2*)&Ps[(rowL    ) * PST + c] = p0;
            *(uint2*)&Ps[(rowL + 8) * PST + c] = p1;
        }
        __syncwarp();

        // O += P @ V
        #pragma unroll
        for (int kb = 0; kb < 32; kb += 8) {
            unsigned a0 = Ps[(rowL    ) * PST + kb + t4];
            unsigned a1 = Ps[(rowL + 8) * PST + kb + t4];
            unsigned a2 = Ps[(rowL    ) * PST + kb + t4 + 4];
            unsigned a3 = Ps[(rowL + 8) * PST + kb + t4 + 4];
            #pragma unroll
            for (int nt = 0; nt < 8; nt++) {
                unsigned b0 = Vs[(kb + t4    ) * VST + nt * 8 + g];
                unsigned b1 = Vs[(kb + t4 + 4) * VST + nt * 8 + g];
                mma_tf32(o[nt], a0, a1, a2, a3, b0, b1);
            }
        }
    }

    // epilogue
    float inv0 = 1.f / l0, inv1 = 1.f / l1;
    #pragma unroll
    for (int nt = 0; nt < 8; nt++) {
        int d = nt * 8 + 2 * t4;
        float2 v0 = make_float2(o[nt][0] * inv0, o[nt][1] * inv0);
        float2 v1 = make_float2(o[nt][2] * inv1, o[nt][3] * inv1);
        *(float2*)(outp + ((size_t)b * T_ + row0) * C_ + h * D_ + d) = v0;
        *(float2*)(outp + ((size_t)b * T_ + row1) * C_ + h * D_ + d) = v1;
    }
}

// ---------------------------------------------------------------------------
extern "C" void kernel_launch(void* const* d_in, const int* in_sizes, int n_in,
                              void* d_out, int out_size)
{
    (void)in_sizes; (void)n_in; (void)out_size;
    const float* x      = (const float*)d_in[0];
    const float* w_attn = (const float*)d_in[1];
    const float* b_attn = (const float*)d_in[2];
    const float* w_proj = (const float*)d_in[3];
    const float* b_proj = (const float*)d_in[4];
    float* out = (float*)d_out;

    float *qkv = nullptr, *att = nullptr;
    cudaGetSymbolAddress((void**)&qkv, g_qkv);
    cudaGetSymbolAddress((void**)&att, g_att);

    gemm_tf32<<<dim3(C3_ / 128, (B_ * T_) / 128), 128>>>(
        x, w_attn, b_attn, qkv, B_ * T_, C3_, C_);

    attn_tf32<<<dim3(T_ / 64, B_ * H_), 128>>>(qkv, att);

    gemm_tf32<<<dim3(C_ / 128, (B_ * T_) / 128), 128>>>(
        att, w_proj, b_proj, out, B_ * T_, C_, C_);
}

// round 5
// speedup vs baseline: 1.5842x; 1.1227x over previous
#include <cuda_runtime.h>
#include <math.h>

#define B_   8
#define T_   1024
#define C_   768
#define H_   12
#define D_   64
#define C3_  2304

__device__ float g_qkv[(size_t)B_ * T_ * C3_];   // [B,T,3C]
__device__ float g_att[(size_t)B_ * T_ * C_];    // [B,T,C]

// ---------------------------------------------------------------------------
__device__ __forceinline__ unsigned f2tf32(float x) {
    unsigned u;
    asm("cvt.rna.tf32.f32 %0, %1;" : "=r"(u) : "f"(x));
    return u;
}

__device__ __forceinline__ uint4 f2tf32x4(float4 v) {
    uint4 u;
    u.x = f2tf32(v.x); u.y = f2tf32(v.y); u.z = f2tf32(v.z); u.w = f2tf32(v.w);
    return u;
}

__device__ __forceinline__ void mma_tf32(float c[4],
    unsigned a0, unsigned a1, unsigned a2, unsigned a3,
    unsigned b0, unsigned b1)
{
    asm volatile(
        "mma.sync.aligned.m16n8k8.row.col.f32.tf32.tf32.f32 "
        "{%0,%1,%2,%3}, {%4,%5,%6,%7}, {%8,%9}, {%0,%1,%2,%3};\n"
        : "+f"(c[0]), "+f"(c[1]), "+f"(c[2]), "+f"(c[3])
        : "r"(a0), "r"(a1), "r"(a2), "r"(a3), "r"(b0), "r"(b1));
}

// ldmatrix x4: 4 8x8 matrices of 16-bit-viewed data; for tf32 each 16B row
// holds 4 tf32 and lane 4r+c receives word c of row r (exactly frag layout).
__device__ __forceinline__ void ldsm_x4(unsigned& d0, unsigned& d1,
                                        unsigned& d2, unsigned& d3,
                                        unsigned saddr)
{
    asm volatile(
        "ldmatrix.sync.aligned.m8n8.x4.shared.b16 {%0,%1,%2,%3}, [%4];\n"
        : "=r"(d0), "=r"(d1), "=r"(d2), "=r"(d3) : "r"(saddr));
}

// ---------------------------------------------------------------------------
// TF32 GEMM: Cout[M,N] = A[M,K] @ W[K,N] + bias
// 128x128 block tile, BK=16, 256 threads = 8 warps (2m x 4n), warp 64x32.
// A fragments via ldmatrix.x4; B via conflict-free scalar LDS.
// ---------------------------------------------------------------------------
#define AST 20    // As row stride (16 k + 4 pad) words
#define BST 136   // Bs row stride (128 n + 8 pad) words

__global__ __launch_bounds__(256) void gemm_tf32(
    const float* __restrict__ A, const float* __restrict__ W,
    const float* __restrict__ bias, float* __restrict__ Cout,
    int M, int N, int K)
{
    __shared__ __align__(16) unsigned As[2][128 * AST];
    __shared__ __align__(16) unsigned Bs[2][16 * BST];

    const int tid  = threadIdx.x;
    const int lane = tid & 31;
    const int wid  = tid >> 5;
    const int wm   = wid >> 2;           // 0..1
    const int wn   = wid & 3;            // 0..3
    const int g    = lane >> 2;          // 0..7
    const int t4   = lane & 3;           // 0..3

    const int rowBase = blockIdx.y * 128;
    const int colBase = blockIdx.x * 128;

    // ldmatrix per-lane row-offset (words):
    // mat0: row g           k+0 | mat1: row g+8 k+0
    // mat2: row g           k+4 | mat3: row g+8 k+4
    const unsigned aoff = ((lane & 7) + ((lane >> 3) & 1) * 8) * AST
                        + ((lane >> 4) & 1) * 4;
    const unsigned As_base = (unsigned)__cvta_generic_to_shared(&As[0][0]);
    const unsigned Bs_base = (unsigned)__cvta_generic_to_shared(&Bs[0][0]);

    float acc[4][4][4];
    #pragma unroll
    for (int i = 0; i < 4; i++)
        #pragma unroll
        for (int j = 0; j < 4; j++)
            #pragma unroll
            for (int q = 0; q < 4; q++) acc[i][j][q] = 0.f;

    // loader roles (256 threads): A: thread -> row tid>>1, k-half (tid&1)*8
    const int aR  = tid >> 1;
    const int aKb = (tid & 1) * 8;
    const int bK  = tid >> 4;            // 0..15
    const int bC  = (tid & 15) * 8;      // 8 consecutive n per thread

    float4 av0, av1, bv0, bv1;
    av0 = *(const float4*)(A + (size_t)(rowBase + aR) * K + aKb);
    av1 = *(const float4*)(A + (size_t)(rowBase + aR) * K + aKb + 4);
    bv0 = *(const float4*)(W + (size_t)bK * N + colBase + bC);
    bv1 = *(const float4*)(W + (size_t)bK * N + colBase + bC + 4);
    *(uint4*)&As[0][aR * AST + aKb]     = f2tf32x4(av0);
    *(uint4*)&As[0][aR * AST + aKb + 4] = f2tf32x4(av1);
    *(uint4*)&Bs[0][bK * BST + bC]      = f2tf32x4(bv0);
    *(uint4*)&Bs[0][bK * BST + bC + 4]  = f2tf32x4(bv1);
    __syncthreads();

    const int nstage = K / 16;
    for (int s = 0; s < nstage; s++) {
        const int buf = s & 1;
        if (s + 1 < nstage) {
            const int k0 = (s + 1) * 16;
            av0 = *(const float4*)(A + (size_t)(rowBase + aR) * K + k0 + aKb);
            av1 = *(const float4*)(A + (size_t)(rowBase + aR) * K + k0 + aKb + 4);
            bv0 = *(const float4*)(W + (size_t)(k0 + bK) * N + colBase + bC);
            bv1 = *(const float4*)(W + (size_t)(k0 + bK) * N + colBase + bC + 4);
        }

        const unsigned abase = As_base + (unsigned)buf * (128 * AST * 4)
                             + (aoff + (unsigned)(wm * 64) * AST) * 4;
        const unsigned* bb = &Bs[buf][0];
        #pragma unroll
        for (int kb = 0; kb < 16; kb += 8) {
            unsigned af[4][4];
            #pragma unroll
            for (int mt = 0; mt < 4; mt++)
                ldsm_x4(af[mt][0], af[mt][1], af[mt][2], af[mt][3],
                        abase + (unsigned)(mt * 16 * AST + kb) * 4);
            unsigned bf[4][2];
            #pragma unroll
            for (int nt = 0; nt < 4; nt++) {
                int c0 = wn * 32 + nt * 8 + g;
                bf[nt][0] = bb[(kb + t4    ) * BST + c0];
                bf[nt][1] = bb[(kb + t4 + 4) * BST + c0];
            }
            #pragma unroll
            for (int mt = 0; mt < 4; mt++)
                #pragma unroll
                for (int nt = 0; nt < 4; nt++)
                    mma_tf32(acc[mt][nt], af[mt][0], af[mt][1], af[mt][2], af[mt][3],
                             bf[nt][0], bf[nt][1]);
        }

        if (s + 1 < nstage) {
            unsigned* aw = &As[buf ^ 1][0];
            unsigned* bw = &Bs[buf ^ 1][0];
            *(uint4*)&aw[aR * AST + aKb]     = f2tf32x4(av0);
            *(uint4*)&aw[aR * AST + aKb + 4] = f2tf32x4(av1);
            *(uint4*)&bw[bK * BST + bC]      = f2tf32x4(bv0);
            *(uint4*)&bw[bK * BST + bC + 4]  = f2tf32x4(bv1);
        }
        __syncthreads();
    }

    // epilogue
    #pragma unroll
    for (int mt = 0; mt < 4; mt++) {
        #pragma unroll
        for (int nt = 0; nt < 4; nt++) {
            int r0 = rowBase + wm * 64 + mt * 16 + g;
            int c  = colBase + wn * 32 + nt * 8 + 2 * t4;
            float bx = bias[c], by = bias[c + 1];
            float2 v0 = make_float2(acc[mt][nt][0] + bx, acc[mt][nt][1] + by);
            float2 v1 = make_float2(acc[mt][nt][2] + bx, acc[mt][nt][3] + by);
            *(float2*)(Cout + (size_t)r0 * N + c)       = v0;
            *(float2*)(Cout + (size_t)(r0 + 8) * N + c) = v1;
        }
    }
}

// ---------------------------------------------------------------------------
// Flash causal attention, tf32 mma. 128 threads = 4 warps, 64 q-rows/block,
// 32-key tiles. Q fragments in registers; K and P fragments via ldmatrix.
// ---------------------------------------------------------------------------
#define QST 68
#define KST 68
#define VST 72
#define PST 36

__global__ __launch_bounds__(128) void attn_tf32(
    const float* __restrict__ qkv, float* __restrict__ outp)
{
    __shared__ unsigned Qs[64 * QST];
    __shared__ unsigned Ks[32 * KST];
    __shared__ unsigned Vs[32 * VST];
    __shared__ unsigned Ps[64 * PST];

    const int tid  = threadIdx.x;
    const int lane = tid & 31;
    const int wid  = tid >> 5;           // 0..3
    const int g    = lane >> 2;
    const int t4   = lane & 3;

    const int bh = blockIdx.y;
    const int b  = bh / H_;
    const int h  = bh % H_;
    const int qt = blockIdx.x;
    const int qBase = qt * 64;

    const float* qptr = qkv + (size_t)b * T_ * C3_ + h * D_;
    const float* kptr = qptr + C_;
    const float* vptr = qptr + 2 * C_;

    // ldmatrix per-lane offsets
    // K (B-operand): mat0 row l k+0 | mat1 row l k+4 | mat2 row l+8 k+0 | mat3 row l+8 k+4
    const unsigned koff = ((lane & 7) + ((lane >> 4) & 1) * 8) * KST
                        + ((lane >> 3) & 1) * 4;
    // P (A-operand): mat0 row l k+0 | mat1 row l+8 k+0 | mat2 row l k+4 | mat3 row l+8 k+4
    const unsigned poff = ((lane & 7) + ((lane >> 3) & 1) * 8) * PST
                        + ((lane >> 4) & 1) * 4;
    const unsigned Ks_base = (unsigned)__cvta_generic_to_shared(&Ks[0]);
    const unsigned Ps_base = (unsigned)__cvta_generic_to_shared(&Ps[0]);

    // load Q tile (64x64), tf32
    #pragma unroll
    for (int l = 0; l < 8; l++) {
        int idx = tid + l * 128;
        int r = idx >> 4, c4 = (idx & 15) << 2;
        float4 v = *(const float4*)(qptr + (size_t)(qBase + r) * C3_ + c4);
        *(uint4*)&Qs[r * QST + c4] = f2tf32x4(v);
    }
    __syncthreads();

    const int rowL = wid * 16 + g;
    unsigned qa[8][4];
    #pragma unroll
    for (int kbq = 0; kbq < 8; kbq++) {
        qa[kbq][0] = Qs[(rowL    ) * QST + kbq * 8 + t4];
        qa[kbq][1] = Qs[(rowL + 8) * QST + kbq * 8 + t4];
        qa[kbq][2] = Qs[(rowL    ) * QST + kbq * 8 + t4 + 4];
        qa[kbq][3] = Qs[(rowL + 8) * QST + kbq * 8 + t4 + 4];
    }

    float o[8][4];
    #pragma unroll
    for (int nt = 0; nt < 8; nt++)
        #pragma unroll
        for (int q = 0; q < 4; q++) o[nt][q] = 0.f;
    float m0 = -1e30f, m1 = -1e30f, l0 = 0.f, l1 = 0.f;

    const float scale = 0.125f;
    const int row0 = qBase + rowL;
    const int row1 = row0 + 8;

    const int ktmax = 2 * qt + 1;
    for (int kt = 0; kt <= ktmax; kt++) {
        const int kBase = kt * 32;
        const bool domask = (kt >= 2 * qt);

        __syncthreads();
        #pragma unroll
        for (int l = 0; l < 4; l++) {
            int idx = tid + l * 128;
            int r = idx >> 4, c4 = (idx & 15) << 2;
            float4 kv = *(const float4*)(kptr + (size_t)(kBase + r) * C3_ + c4);
            *(uint4*)&Ks[r * KST + c4] = f2tf32x4(kv);
            float4 vv = *(const float4*)(vptr + (size_t)(kBase + r) * C3_ + c4);
            *(uint4*)&Vs[r * VST + c4] = f2tf32x4(vv);
        }
        __syncthreads();

        // S = Q @ K^T : warp tile 16 x 32, K frags via ldmatrix (2 nt per x4)
        float s[4][4];
        #pragma unroll
        for (int nt = 0; nt < 4; nt++)
            #pragma unroll
            for (int q = 0; q < 4; q++) s[nt][q] = 0.f;

        #pragma unroll
        for (int kb8 = 0; kb8 < 8; kb8++) {
            #pragma unroll
            for (int ntp = 0; ntp < 2; ntp++) {
                unsigned b00, b01, b10, b11;
                ldsm_x4(b00, b01, b10, b11,
                        Ks_base + (koff + (unsigned)(ntp * 16 * KST + kb8 * 8)) * 4);
                mma_tf32(s[ntp * 2 + 0], qa[kb8][0], qa[kb8][1], qa[kb8][2],
                         qa[kb8][3], b00, b01);
                mma_tf32(s[ntp * 2 + 1], qa[kb8][0], qa[kb8][1], qa[kb8][2],
                         qa[kb8][3], b10, b11);
            }
        }

        // scale + causal mask
        #pragma unroll
        for (int nt = 0; nt < 4; nt++) {
            #pragma unroll
            for (int q = 0; q < 4; q++) {
                s[nt][q] *= scale;
                if (domask) {
                    int col = kBase + nt * 8 + 2 * t4 + (q & 1);
                    int row = (q < 2) ? row0 : row1;
                    if (col > row) s[nt][q] = -1e30f;
                }
            }
        }

        // online softmax
        float mt0 = -1e30f, mt1 = -1e30f;
        #pragma unroll
        for (int nt = 0; nt < 4; nt++) {
            mt0 = fmaxf(mt0, fmaxf(s[nt][0], s[nt][1]));
            mt1 = fmaxf(mt1, fmaxf(s[nt][2], s[nt][3]));
        }
        mt0 = fmaxf(mt0, __shfl_xor_sync(0xffffffffu, mt0, 1));
        mt0 = fmaxf(mt0, __shfl_xor_sync(0xffffffffu, mt0, 2));
        mt1 = fmaxf(mt1, __shfl_xor_sync(0xffffffffu, mt1, 1));
        mt1 = fmaxf(mt1, __shfl_xor_sync(0xffffffffu, mt1, 2));

        float mn0 = fmaxf(m0, mt0), mn1 = fmaxf(m1, mt1);
        float al0 = __expf(m0 - mn0), al1 = __expf(m1 - mn1);
        m0 = mn0; m1 = mn1;

        float rs0 = 0.f, rs1 = 0.f;
        #pragma unroll
        for (int nt = 0; nt < 4; nt++) {
            s[nt][0] = __expf(s[nt][0] - mn0);
            s[nt][1] = __expf(s[nt][1] - mn0);
            s[nt][2] = __expf(s[nt][2] - mn1);
            s[nt][3] = __expf(s[nt][3] - mn1);
            rs0 += s[nt][0] + s[nt][1];
            rs1 += s[nt][2] + s[nt][3];
        }
        rs0 += __shfl_xor_sync(0xffffffffu, rs0, 1);
        rs0 += __shfl_xor_sync(0xffffffffu, rs0, 2);
        rs1 += __shfl_xor_sync(0xffffffffu, rs1, 1);
        rs1 += __shfl_xor_sync(0xffffffffu, rs1, 2);
        l0 = l0 * al0 + rs0;
        l1 = l1 * al1 + rs1;

        #pragma unroll
        for (int nt = 0; nt < 8; nt++) {
            o[nt][0] *= al0; o[nt][1] *= al0;
            o[nt][2] *= al1; o[nt][3] *= al1;
        }

        // stage P -> smem (tf32)
        #pragma unroll
        for (int nt = 0; nt < 4; nt++) {
            int c = nt * 8 + 2 * t4;
            uint2 p0 = make_uint2(f2tf32(s[nt][0]), f2tf32(s[nt][1]));
            uint2 p1 = make_uint2(f2tf32(s[nt][2]), f2tf32(s[nt][3]));
            *(uint2*)&Ps[(rowL    ) * PST + c] = p0;
            *(uint2*)&Ps[(rowL + 8) * PST + c] = p1;
        }
        __syncwarp();

        // O += P @ V ; P frags via ldmatrix
        #pragma unroll
        for (int kbp = 0; kbp < 4; kbp++) {
            unsigned a0, a1, a2, a3;
            ldsm_x4(a0, a1, a2, a3,
                    Ps_base + (poff + (unsigned)(wid * 16 * PST + kbp * 8)) * 4);
            #pragma unroll
            for (int nt = 0; nt < 8; nt++) {
                unsigned b0 = Vs[(kbp * 8 + t4    ) * VST + nt * 8 + g];
                unsigned b1 = Vs[(kbp * 8 + t4 + 4) * VST + nt * 8 + g];
                mma_tf32(o[nt], a0, a1, a2, a3, b0, b1);
            }
        }
    }

    // epilogue
    float inv0 = 1.f / l0, inv1 = 1.f / l1;
    #pragma unroll
    for (int nt = 0; nt < 8; nt++) {
        int d = nt * 8 + 2 * t4;
        float2 v0 = make_float2(o[nt][0] * inv0, o[nt][1] * inv0);
        float2 v1 = make_float2(o[nt][2] * inv1, o[nt][3] * inv1);
        *(float2*)(outp + ((size_t)b * T_ + row0) * C_ + h * D_ + d) = v0;
        *(float2*)(outp + ((size_t)b * T_ + row1) * C_ + h * D_ + d) = v1;
    }
}

// ---------------------------------------------------------------------------
extern "C" void kernel_launch(void* const* d_in, const int* in_sizes, int n_in,
                              void* d_out, int out_size)
{
    (void)in_sizes; (void)n_in; (void)out_size;
    const float* x      = (const float*)d_in[0];
    const float* w_attn = (const float*)d_in[1];
    const float* b_attn = (const float*)d_in[2];
    const float* w_proj = (const float*)d_in[3];
    const float* b_proj = (const float*)d_in[4];
    float* out = (float*)d_out;

    float *qkv = nullptr, *att = nullptr;
    cudaGetSymbolAddress((void**)&qkv, g_qkv);
    cudaGetSymbolAddress((void**)&att, g_att);

    gemm_tf32<<<dim3(C3_ / 128, (B_ * T_) / 128), 256>>>(
        x, w_attn, b_attn, qkv, B_ * T_, C3_, C_);

    attn_tf32<<<dim3(T_ / 64, B_ * H_), 128>>>(qkv, att);

    gemm_tf32<<<dim3(C_ / 128, (B_ * T_) / 128), 256>>>(
        att, w_proj, b_proj, out, B_ * T_, C_, C_);
}

// round 6
// speedup vs baseline: 2.0821x; 1.3143x over previous
#include <cuda_runtime.h>
#include <cuda_fp16.h>
#include <math.h>

#define B_   8
#define T_   1024
#define C_   768
#define H_   12
#define D_   64
#define C3_  2304

__device__ float g_qkv[(size_t)B_ * T_ * C3_];   // [B,T,3C]
__device__ float g_att[(size_t)B_ * T_ * C_];    // [B,T,C]

// ---------------------------------------------------------------------------
__device__ __forceinline__ unsigned f2h2(float x, float y) {
    __half2 h = __floats2half2_rn(x, y);
    return *reinterpret_cast<unsigned*>(&h);
}

__device__ __forceinline__ void mma_f16(float c[4],
    unsigned a0, unsigned a1, unsigned a2, unsigned a3,
    unsigned b0, unsigned b1)
{
    asm volatile(
        "mma.sync.aligned.m16n8k16.row.col.f32.f16.f16.f32 "
        "{%0,%1,%2,%3}, {%4,%5,%6,%7}, {%8,%9}, {%0,%1,%2,%3};\n"
        : "+f"(c[0]), "+f"(c[1]), "+f"(c[2]), "+f"(c[3])
        : "r"(a0), "r"(a1), "r"(a2), "r"(a3), "r"(b0), "r"(b1));
}

__device__ __forceinline__ void ldsm_x4(unsigned& d0, unsigned& d1,
                                        unsigned& d2, unsigned& d3,
                                        unsigned saddr)
{
    asm volatile(
        "ldmatrix.sync.aligned.m8n8.x4.shared.b16 {%0,%1,%2,%3}, [%4];\n"
        : "=r"(d0), "=r"(d1), "=r"(d2), "=r"(d3) : "r"(saddr));
}

__device__ __forceinline__ void ldsm_x4_t(unsigned& d0, unsigned& d1,
                                          unsigned& d2, unsigned& d3,
                                          unsigned saddr)
{
    asm volatile(
        "ldmatrix.sync.aligned.m8n8.x4.trans.shared.b16 {%0,%1,%2,%3}, [%4];\n"
        : "=r"(d0), "=r"(d1), "=r"(d2), "=r"(d3) : "r"(saddr));
}

// ---------------------------------------------------------------------------
// FP16 GEMM: Cout[M,N] = A[M,K] @ W[K,N] + bias   (fp32 accumulate)
// 128x128 block tile, BK=32, 256 threads = 8 warps (2m x 4n), warp 64x32.
// A frags: ldmatrix.x4 ; B frags: ldmatrix.x4.trans. Zero scalar LDS in loop.
// ---------------------------------------------------------------------------
#define AST2 40    // As row stride in halves (32 k + 8 pad)
#define BST2 136   // Bs row stride in halves (128 n + 8 pad)

__global__ __launch_bounds__(256) void gemm_f16(
    const float* __restrict__ A, const float* __restrict__ W,
    const float* __restrict__ bias, float* __restrict__ Cout,
    int M, int N, int K)
{
    __shared__ __align__(16) __half As[2][128 * AST2];
    __shared__ __align__(16) __half Bs[2][32 * BST2];

    const int tid  = threadIdx.x;
    const int lane = tid & 31;
    const int wid  = tid >> 5;
    const int wm   = wid >> 2;           // 0..1
    const int wn   = wid & 3;            // 0..3
    const int g    = lane >> 2;          // 0..7
    const int t4   = lane & 3;           // 0..3

    const int rowBase = blockIdx.y * 128;
    const int colBase = blockIdx.x * 128;

    // ldmatrix per-lane offsets (halves)
    // A (non-trans): lanes 0-7 rows 0-7 k0 | 8-15 rows 8-15 k0 | 16-23 rows 0-7 k+8 | 24-31 rows 8-15 k+8
    const unsigned aoff = ((lane & 7) + ((lane >> 3) & 1) * 8) * AST2
                        + ((lane >> 4) & 1) * 8;
    // B (trans over [k][n]): lanes 0-7 k0-7 n0 | 8-15 k8-15 n0 | 16-23 k0-7 n+8 | 24-31 k8-15 n+8
    const unsigned boff = ((lane & 7) + ((lane >> 3) & 1) * 8) * BST2
                        + ((lane >> 4) & 1) * 8;
    const unsigned As_base = (unsigned)__cvta_generic_to_shared(&As[0][0]);
    const unsigned Bs_base = (unsigned)__cvta_generic_to_shared(&Bs[0][0]);

    float acc[4][4][4];
    #pragma unroll
    for (int i = 0; i < 4; i++)
        #pragma unroll
        for (int j = 0; j < 4; j++)
            #pragma unroll
            for (int q = 0; q < 4; q++) acc[i][j][q] = 0.f;

    // loader roles: A: 2 thr/row, 16 halves each; B: 8 thr/row, 16 halves each
    const int aR = tid >> 1, aC = (tid & 1) * 16;
    const int bK = tid >> 3, bC = (tid & 7) * 16;

    float4 av0, av1, av2, av3, bv0, bv1, bv2, bv3;
    #define GLOAD(k0) \
        av0 = *(const float4*)(A + (size_t)(rowBase + aR) * K + (k0) + aC);      \
        av1 = *(const float4*)(A + (size_t)(rowBase + aR) * K + (k0) + aC + 4);  \
        av2 = *(const float4*)(A + (size_t)(rowBase + aR) * K + (k0) + aC + 8);  \
        av3 = *(const float4*)(A + (size_t)(rowBase + aR) * K + (k0) + aC + 12); \
        bv0 = *(const float4*)(W + (size_t)((k0) + bK) * N + colBase + bC);      \
        bv1 = *(const float4*)(W + (size_t)((k0) + bK) * N + colBase + bC + 4);  \
        bv2 = *(const float4*)(W + (size_t)((k0) + bK) * N + colBase + bC + 8);  \
        bv3 = *(const float4*)(W + (size_t)((k0) + bK) * N + colBase + bC + 12);

    #define SSTORE(buf) {                                                        \
        uint4 ua0 = make_uint4(f2h2(av0.x, av0.y), f2h2(av0.z, av0.w),           \
                               f2h2(av1.x, av1.y), f2h2(av1.z, av1.w));          \
        uint4 ua1 = make_uint4(f2h2(av2.x, av2.y), f2h2(av2.z, av2.w),           \
                               f2h2(av3.x, av3.y), f2h2(av3.z, av3.w));          \
        *(uint4*)&As[buf][aR * AST2 + aC]     = ua0;                             \
        *(uint4*)&As[buf][aR * AST2 + aC + 8] = ua1;                             \
        uint4 ub0 = make_uint4(f2h2(bv0.x, bv0.y), f2h2(bv0.z, bv0.w),           \
                               f2h2(bv1.x, bv1.y), f2h2(bv1.z, bv1.w));          \
        uint4 ub1 = make_uint4(f2h2(bv2.x, bv2.y), f2h2(bv2.z, bv2.w),           \
                               f2h2(bv3.x, bv3.y), f2h2(bv3.z, bv3.w));          \
        *(uint4*)&Bs[buf][bK * BST2 + bC]     = ub0;                             \
        *(uint4*)&Bs[buf][bK * BST2 + bC + 8] = ub1;                             \
    }

    GLOAD(0);
    SSTORE(0);
    __syncthreads();

    const int nstage = K / 32;
    for (int s = 0; s < nstage; s++) {
        const int buf = s & 1;
        if (s + 1 < nstage) { GLOAD((s + 1) * 32); }

        const unsigned abase = As_base + (unsigned)buf * (128 * AST2 * 2)
                             + (aoff + (unsigned)(wm * 64) * AST2) * 2;
        const unsigned bbase = Bs_base + (unsigned)buf * (32 * BST2 * 2)
                             + (boff + (unsigned)(wn * 32)) * 2;
        #pragma unroll
        for (int kb = 0; kb < 2; kb++) {
            unsigned af[4][4];
            #pragma unroll
            for (int mt = 0; mt < 4; mt++)
                ldsm_x4(af[mt][0], af[mt][1], af[mt][2], af[mt][3],
                        abase + (unsigned)(mt * 16 * AST2 + kb * 16) * 2);
            unsigned bf[4][2];
            #pragma unroll
            for (int ntp = 0; ntp < 2; ntp++) {
                unsigned d0, d1, d2, d3;
                ldsm_x4_t(d0, d1, d2, d3,
                          bbase + (unsigned)(kb * 16 * BST2 + ntp * 16) * 2);
                bf[ntp * 2 + 0][0] = d0; bf[ntp * 2 + 0][1] = d1;
                bf[ntp * 2 + 1][0] = d2; bf[ntp * 2 + 1][1] = d3;
            }
            #pragma unroll
            for (int mt = 0; mt < 4; mt++)
                #pragma unroll
                for (int nt = 0; nt < 4; nt++)
                    mma_f16(acc[mt][nt], af[mt][0], af[mt][1], af[mt][2], af[mt][3],
                            bf[nt][0], bf[nt][1]);
        }

        if (s + 1 < nstage) { SSTORE(buf ^ 1); }
        __syncthreads();
    }
    #undef GLOAD
    #undef SSTORE

    // epilogue (fp32 accumulators + bias)
    #pragma unroll
    for (int mt = 0; mt < 4; mt++) {
        #pragma unroll
        for (int nt = 0; nt < 4; nt++) {
            int r0 = rowBase + wm * 64 + mt * 16 + g;
            int c  = colBase + wn * 32 + nt * 8 + 2 * t4;
            float bx = bias[c], by = bias[c + 1];
            float2 v0 = make_float2(acc[mt][nt][0] + bx, acc[mt][nt][1] + by);
            float2 v1 = make_float2(acc[mt][nt][2] + bx, acc[mt][nt][3] + by);
            *(float2*)(Cout + (size_t)r0 * N + c)       = v0;
            *(float2*)(Cout + (size_t)(r0 + 8) * N + c) = v1;
        }
    }
}

// ---------------------------------------------------------------------------
// Flash causal attention, fp16 mma (fp32 softmax + accum).
// 128 threads = 4 warps, 64 q-rows/block, 32-key tiles.
// Q frags hoisted in regs; K via ldmatrix (non-trans, [n][k] layout);
// V via ldmatrix.trans ([k][n]); P via ldmatrix (A-frag).
// ---------------------------------------------------------------------------
#define QST2 72
#define KST2 72
#define VST2 72
#define PST2 40

__global__ __launch_bounds__(128) void attn_f16(
    const float* __restrict__ qkv, float* __restrict__ outp)
{
    __shared__ __align__(16) __half Qs[64 * QST2];
    __shared__ __align__(16) __half Ks[32 * KST2];
    __shared__ __align__(16) __half Vs[32 * VST2];
    __shared__ __align__(16) __half Ps[64 * PST2];

    const int tid  = threadIdx.x;
    const int lane = tid & 31;
    const int wid  = tid >> 5;           // 0..3
    const int g    = lane >> 2;
    const int t4   = lane & 3;

    const int bh = blockIdx.y;
    const int b  = bh / H_;
    const int h  = bh % H_;
    const int qt = blockIdx.x;
    const int qBase = qt * 64;

    const float* qptr = qkv + (size_t)b * T_ * C3_ + h * D_;
    const float* kptr = qptr + C_;
    const float* vptr = qptr + 2 * C_;

    // ldmatrix per-lane offsets (halves)
    const unsigned qoff = ((lane & 7) + ((lane >> 3) & 1) * 8) * QST2
                        + ((lane >> 4) & 1) * 8;                     // A-frag
    const unsigned koff = ((lane & 7) + ((lane >> 4) & 1) * 8) * KST2
                        + ((lane >> 3) & 1) * 8;                     // B non-trans
    const unsigned voff = ((lane & 7) + ((lane >> 3) & 1) * 8) * VST2
                        + ((lane >> 4) & 1) * 8;                     // B trans
    const unsigned poff = ((lane & 7) + ((lane >> 3) & 1) * 8) * PST2
                        + ((lane >> 4) & 1) * 8;                     // A-frag
    const unsigned Qs_base = (unsigned)__cvta_generic_to_shared(&Qs[0]);
    const unsigned Ks_base = (unsigned)__cvta_generic_to_shared(&Ks[0]);
    const unsigned Vs_base = (unsigned)__cvta_generic_to_shared(&Vs[0]);
    const unsigned Ps_base = (unsigned)__cvta_generic_to_shared(&Ps[0]);

    // stage Q tile (64x64) as fp16
    #pragma unroll
    for (int l = 0; l < 4; l++) {
        int idx = tid + l * 128;              // 0..511 chunks of 8 floats
        int r = idx >> 3, c8 = (idx & 7) << 3;
        float4 v0 = *(const float4*)(qptr + (size_t)(qBase + r) * C3_ + c8);
        float4 v1 = *(const float4*)(qptr + (size_t)(qBase + r) * C3_ + c8 + 4);
        *(uint4*)&Qs[r * QST2 + c8] =
            make_uint4(f2h2(v0.x, v0.y), f2h2(v0.z, v0.w),
                       f2h2(v1.x, v1.y), f2h2(v1.z, v1.w));
    }
    __syncthreads();

    // hoist Q fragments (4 k16-steps)
    unsigned qa[4][4];
    #pragma unroll
    for (int kq = 0; kq < 4; kq++)
        ldsm_x4(qa[kq][0], qa[kq][1], qa[kq][2], qa[kq][3],
                Qs_base + (qoff + (unsigned)(wid * 16 * QST2 + kq * 16)) * 2);

    float o[8][4];
    #pragma unroll
    for (int nt = 0; nt < 8; nt++)
        #pragma unroll
        for (int q = 0; q < 4; q++) o[nt][q] = 0.f;
    float m0 = -1e30f, m1 = -1e30f, l0 = 0.f, l1 = 0.f;

    const float scale = 0.125f;
    const int rowL = wid * 16 + g;
    const int row0 = qBase + rowL;
    const int row1 = row0 + 8;

    const int ktmax = 2 * qt + 1;
    for (int kt = 0; kt <= ktmax; kt++) {
        const int kBase = kt * 32;
        const bool domask = (kt >= 2 * qt);

        __syncthreads();
        #pragma unroll
        for (int l = 0; l < 2; l++) {
            int idx = tid + l * 128;          // 0..255 chunks of 8 floats
            int r = idx >> 3, c8 = (idx & 7) << 3;
            float4 k0 = *(const float4*)(kptr + (size_t)(kBase + r) * C3_ + c8);
            float4 k1 = *(const float4*)(kptr + (size_t)(kBase + r) * C3_ + c8 + 4);
            *(uint4*)&Ks[r * KST2 + c8] =
                make_uint4(f2h2(k0.x, k0.y), f2h2(k0.z, k0.w),
                           f2h2(k1.x, k1.y), f2h2(k1.z, k1.w));
            float4 v0 = *(const float4*)(vptr + (size_t)(kBase + r) * C3_ + c8);
            float4 v1 = *(const float4*)(vptr + (size_t)(kBase + r) * C3_ + c8 + 4);
            *(uint4*)&Vs[r * VST2 + c8] =
                make_uint4(f2h2(v0.x, v0.y), f2h2(v0.z, v0.w),
                           f2h2(v1.x, v1.y), f2h2(v1.z, v1.w));
        }
        __syncthreads();

        // S = Q @ K^T : warp tile 16 x 32
        float s[4][4];
        #pragma unroll
        for (int nt = 0; nt < 4; nt++)
            #pragma unroll
            for (int q = 0; q < 4; q++) s[nt][q] = 0.f;

        #pragma unroll
        for (int kq = 0; kq < 4; kq++) {
            #pragma unroll
            for (int ntp = 0; ntp < 2; ntp++) {
                unsigned d0, d1, d2, d3;
                ldsm_x4(d0, d1, d2, d3,
                        Ks_base + (koff + (unsigned)(ntp * 16 * KST2 + kq * 16)) * 2);
                mma_f16(s[ntp * 2 + 0], qa[kq][0], qa[kq][1], qa[kq][2], qa[kq][3],
                        d0, d1);
                mma_f16(s[ntp * 2 + 1], qa[kq][0], qa[kq][1], qa[kq][2], qa[kq][3],
                        d2, d3);
            }
        }

        // scale + causal mask (fp32 regs)
        #pragma unroll
        for (int nt = 0; nt < 4; nt++) {
            #pragma unroll
            for (int q = 0; q < 4; q++) {
                s[nt][q] *= scale;
                if (domask) {
                    int col = kBase + nt * 8 + 2 * t4 + (q & 1);
                    int row = (q < 2) ? row0 : row1;
                    if (col > row) s[nt][q] = -1e30f;
                }
            }
        }

        // online softmax
        float mt0 = -1e30f, mt1 = -1e30f;
        #pragma unroll
        for (int nt = 0; nt < 4; nt++) {
            mt0 = fmaxf(mt0, fmaxf(s[nt][0], s[nt][1]));
            mt1 = fmaxf(mt1, fmaxf(s[nt][2], s[nt][3]));
        }
        mt0 = fmaxf(mt0, __shfl_xor_sync(0xffffffffu, mt0, 1));
        mt0 = fmaxf(mt0, __shfl_xor_sync(0xffffffffu, mt0, 2));
        mt1 = fmaxf(mt1, __shfl_xor_sync(0xffffffffu, mt1, 1));
        mt1 = fmaxf(mt1, __shfl_xor_sync(0xffffffffu, mt1, 2));

        float mn0 = fmaxf(m0, mt0), mn1 = fmaxf(m1, mt1);
        float al0 = __expf(m0 - mn0), al1 = __expf(m1 - mn1);
        m0 = mn0; m1 = mn1;

        float rs0 = 0.f, rs1 = 0.f;
        #pragma unroll
        for (int nt = 0; nt < 4; nt++) {
            s[nt][0] = __expf(s[nt][0] - mn0);
            s[nt][1] = __expf(s[nt][1] - mn0);
            s[nt][2] = __expf(s[nt][2] - mn1);
            s[nt][3] = __expf(s[nt][3] - mn1);
            rs0 += s[nt][0] + s[nt][1];
            rs1 += s[nt][2] + s[nt][3];
        }
        rs0 += __shfl_xor_sync(0xffffffffu, rs0, 1);
        rs0 += __shfl_xor_sync(0xffffffffu, rs0, 2);
        rs1 += __shfl_xor_sync(0xffffffffu, rs1, 1);
        rs1 += __shfl_xor_sync(0xffffffffu, rs1, 2);
        l0 = l0 * al0 + rs0;
        l1 = l1 * al1 + rs1;

        #pragma unroll
        for (int nt = 0; nt < 8; nt++) {
            o[nt][0] *= al0; o[nt][1] *= al0;
            o[nt][2] *= al1; o[nt][3] *= al1;
        }

        // stage P -> smem (fp16)
        #pragma unroll
        for (int nt = 0; nt < 4; nt++) {
            int c = nt * 8 + 2 * t4;
            *(unsigned*)&Ps[(rowL    ) * PST2 + c] = f2h2(s[nt][0], s[nt][1]);
            *(unsigned*)&Ps[(rowL + 8) * PST2 + c] = f2h2(s[nt][2], s[nt][3]);
        }
        __syncwarp();

        // O += P @ V
        #pragma unroll
        for (int kb = 0; kb < 2; kb++) {
            unsigned a0, a1, a2, a3;
            ldsm_x4(a0, a1, a2, a3,
                    Ps_base + (poff + (unsigned)(wid * 16 * PST2 + kb * 16)) * 2);
            #pragma unroll
            for (int ntp = 0; ntp < 4; ntp++) {
                unsigned d0, d1, d2, d3;
                ldsm_x4_t(d0, d1, d2, d3,
                          Vs_base + (voff + (unsigned)(kb * 16 * VST2 + ntp * 16)) * 2);
                mma_f16(o[ntp * 2 + 0], a0, a1, a2, a3, d0, d1);
                mma_f16(o[ntp * 2 + 1], a0, a1, a2, a3, d2, d3);
            }
        }
    }

    // epilogue
    float inv0 = 1.f / l0, inv1 = 1.f / l1;
    #pragma unroll
    for (int nt = 0; nt < 8; nt++) {
        int d = nt * 8 + 2 * t4;
        float2 v0 = make_float2(o[nt][0] * inv0, o[nt][1] * inv0);
        float2 v1 = make_float2(o[nt][2] * inv1, o[nt][3] * inv1);
        *(float2*)(outp + ((size_t)b * T_ + row0) * C_ + h * D_ + d) = v0;
        *(float2*)(outp + ((size_t)b * T_ + row1) * C_ + h * D_ + d) = v1;
    }
}

// ---------------------------------------------------------------------------
extern "C" void kernel_launch(void* const* d_in, const int* in_sizes, int n_in,
                              void* d_out, int out_size)
{
    (void)in_sizes; (void)n_in; (void)out_size;
    const float* x      = (const float*)d_in[0];
    const float* w_attn = (const float*)d_in[1];
    const float* b_attn = (const float*)d_in[2];
    const float* w_proj = (const float*)d_in[3];
    const float* b_proj = (const float*)d_in[4];
    float* out = (float*)d_out;

    float *qkv = nullptr, *att = nullptr;
    cudaGetSymbolAddress((void**)&qkv, g_qkv);
    cudaGetSymbolAddress((void**)&att, g_att);

    gemm_f16<<<dim3(C3_ / 128, (B_ * T_) / 128), 256>>>(
        x, w_attn, b_attn, qkv, B_ * T_, C3_, C_);

    attn_f16<<<dim3(T_ / 64, B_ * H_), 128>>>(qkv, att);

    gemm_f16<<<dim3(C_ / 128, (B_ * T_) / 128), 256>>>(
        att, w_proj, b_proj, out, B_ * T_, C_, C_);
}

// round 8
// speedup vs baseline: 2.7970x; 1.3433x over previous
#include <cuda_runtime.h>
#include <cuda_fp16.h>
#include <cstdint>

#define B_   8
#define T_   1024
#define C_   768
#define H_   12
#define D_   64
#define C3_  2304
#define MT_  (B_ * T_)      // 8192 rows

// fp16 intermediates / prepped operands
__device__ __half g_qkv_h[(size_t)MT_ * C3_];  // [t][3C]
__device__ __half g_att_h[(size_t)MT_ * C_];   // [t][C]
__device__ __half g_xh  [(size_t)MT_ * C_];    // x as fp16
__device__ __half g_waT [(size_t)C3_ * C_];    // w_attn^T  [N=2304][K=768]
__device__ __half g_wpT [(size_t)C_  * C_];    // w_proj^T  [768][768]

// ---------------------------------------------------------------------------
__device__ __forceinline__ unsigned f2h2(float x, float y) {
    __half2 h = __floats2half2_rn(x, y);
    return *reinterpret_cast<unsigned*>(&h);
}
__device__ __forceinline__ uint32_t s2u(const void* p) {
    return (uint32_t)__cvta_generic_to_shared(p);
}
__device__ __forceinline__ void mma_f16(float c[4],
    unsigned a0, unsigned a1, unsigned a2, unsigned a3,
    unsigned b0, unsigned b1)
{
    asm volatile(
        "mma.sync.aligned.m16n8k16.row.col.f32.f16.f16.f32 "
        "{%0,%1,%2,%3}, {%4,%5,%6,%7}, {%8,%9}, {%0,%1,%2,%3};\n"
        : "+f"(c[0]), "+f"(c[1]), "+f"(c[2]), "+f"(c[3])
        : "r"(a0), "r"(a1), "r"(a2), "r"(a3), "r"(b0), "r"(b1));
}
__device__ __forceinline__ void ldsm_x4(unsigned& d0, unsigned& d1,
                                        unsigned& d2, unsigned& d3, unsigned saddr)
{
    asm volatile("ldmatrix.sync.aligned.m8n8.x4.shared.b16 {%0,%1,%2,%3}, [%4];\n"
                 : "=r"(d0), "=r"(d1), "=r"(d2), "=r"(d3) : "r"(saddr));
}
__device__ __forceinline__ void ldsm_x4_t(unsigned& d0, unsigned& d1,
                                          unsigned& d2, unsigned& d3, unsigned saddr)
{
    asm volatile("ldmatrix.sync.aligned.m8n8.x4.trans.shared.b16 {%0,%1,%2,%3}, [%4];\n"
                 : "=r"(d0), "=r"(d1), "=r"(d2), "=r"(d3) : "r"(saddr));
}
__device__ __forceinline__ void cp16(uint32_t saddr, const void* gaddr) {
    asm volatile("cp.async.cg.shared.global [%0], [%1], 16;"
                 :: "r"(saddr), "l"(gaddr));
}
#define CP_COMMIT()  asm volatile("cp.async.commit_group;" ::: "memory")
#define CP_WAIT0()   asm volatile("cp.async.wait_group 0;" ::: "memory")

// ---------------------------------------------------------------------------
// prep kernels
// ---------------------------------------------------------------------------
__global__ void cvt_x_kernel(const float* __restrict__ x, __half* __restrict__ xh,
                             int n4) {
    int i = blockIdx.x * blockDim.x + threadIdx.x;
    if (i < n4) {
        float4 v = ((const float4*)x)[i];
        uint2 h;
        h.x = f2h2(v.x, v.y);
        h.y = f2h2(v.z, v.w);
        ((uint2*)xh)[i] = h;
    }
}

// wt[n][k] = (half) w[k][n]
__global__ __launch_bounds__(256) void transpose_cvt_kernel(
    const float* __restrict__ w, __half* __restrict__ wt, int K, int N)
{
    __shared__ float tile[32][33];
    int n0 = blockIdx.x * 32, k0 = blockIdx.y * 32;
    int tx = threadIdx.x & 31, ty = threadIdx.x >> 5;
    #pragma unroll
    for (int i = ty; i < 32; i += 8)
        tile[i][tx] = w[(size_t)(k0 + i) * N + n0 + tx];
    __syncthreads();
    #pragma unroll
    for (int i = ty; i < 32; i += 8)
        wt[(size_t)(n0 + i) * K + k0 + tx] = __float2half(tile[tx][i]);
}

// ---------------------------------------------------------------------------
// FP16 GEMM, cp.async pipeline: Cout[M,N] = A[M,K] @ Bt[N,K]^T + bias
// A and Bt both fp16 K-major. 128x128 tile, BK=32, 256 thr = 8 warps (2m x 4n),
// warp tile 64x32. All fragments via non-trans ldmatrix. fp32 accumulate.
// ---------------------------------------------------------------------------
#define GST 40   // smem row stride in halves (32 k + 8 pad); 80 B, 16B-aligned

template<bool HALF_OUT>
__global__ __launch_bounds__(256) void gemm_f16ca(
    const __half* __restrict__ A, const __half* __restrict__ Bt,
    const float* __restrict__ bias, void* __restrict__ Cout,
    int M, int N, int K)
{
    __shared__ __align__(16) __half As[2][128 * GST];
    __shared__ __align__(16) __half Bs[2][128 * GST];

    const int tid  = threadIdx.x;
    const int lane = tid & 31;
    const int wid  = tid >> 5;
    const int wm   = wid >> 2;           // 0..1
    const int wn   = wid & 3;            // 0..3
    const int g    = lane >> 2;          // 0..7
    const int t4   = lane & 3;           // 0..3

    const int rowBase = blockIdx.y * 128;
    const int colBase = blockIdx.x * 128;

    // A-frag (non-trans): lanes 0-7 rows r0-7 k0 | 8-15 rows 8-15 k0
    //                     16-23 rows 0-7 k8 | 24-31 rows 8-15 k8
    const unsigned aoff = ((lane & 7) + ((lane >> 3) & 1) * 8) * GST
                        + ((lane >> 4) & 1) * 8;
    // B-frag (non-trans over [n][k]): 0-7 n0-7 k0 | 8-15 n0-7 k8
    //                                 16-23 n8-15 k0 | 24-31 n8-15 k8
    const unsigned boff = ((lane & 7) + ((lane >> 4) & 1) * 8) * GST
                        + ((lane >> 3) & 1) * 8;
    const unsigned As_base = s2u(&As[0][0]);
    const unsigned Bs_base = s2u(&Bs[0][0]);
    const unsigned BUFB = 128 * GST * 2;   // bytes per buffer

    float acc[4][4][4];
    #pragma unroll
    for (int i = 0; i < 4; i++)
        #pragma unroll
        for (int j = 0; j < 4; j++)
            #pragma unroll
            for (int q = 0; q < 4; q++) acc[i][j][q] = 0.f;

    // loader: thread -> row tid>>1, two 16B chunks at k halves (tid&1)*16 + {0,8}
    const int ldR = tid >> 1;
    const int ldC = (tid & 1) * 16;
    const __half* gA = A  + (size_t)(rowBase + ldR) * K + ldC;
    const __half* gB = Bt + (size_t)(colBase + ldR) * K + ldC;
    const unsigned sA = As_base + (unsigned)(ldR * GST + ldC) * 2;
    const unsigned sB = Bs_base + (unsigned)(ldR * GST + ldC) * 2;

    #define ISSUE(s) {                                         \
        const unsigned bo = ((s) & 1) * BUFB;                  \
        const __half* ga = gA + (size_t)(s) * 32;              \
        const __half* gb = gB + (size_t)(s) * 32;              \
        cp16(sA + bo,      ga);                                \
        cp16(sA + bo + 16, ga + 8);                            \
        cp16(sB + bo,      gb);                                \
        cp16(sB + bo + 16, gb + 8);                            \
        CP_COMMIT();                                           \
    }

    const int NS = K / 32;
    ISSUE(0);

    for (int s = 0; s < NS; s++) {
        CP_WAIT0();
        __syncthreads();                 // stage s visible to all
        if (s + 1 < NS) ISSUE(s + 1);    // other buffer; safe (prev sync)

        const unsigned abase = As_base + ((unsigned)(s & 1)) * BUFB
                             + (aoff + (unsigned)(wm * 64) * GST) * 2;
        const unsigned bbase = Bs_base + ((unsigned)(s & 1)) * BUFB
                             + (boff + (unsigned)(wn * 32) * GST) * 2;
        #pragma unroll
        for (int kb = 0; kb < 2; kb++) {
            unsigned af[4][4];
            #pragma unroll
            for (int mt = 0; mt < 4; mt++)
                ldsm_x4(af[mt][0], af[mt][1], af[mt][2], af[mt][3],
                        abase + (unsigned)(mt * 16 * GST + kb * 16) * 2);
            unsigned bf[4][2];
            #pragma unroll
            for (int ntp = 0; ntp < 2; ntp++) {
                unsigned d0, d1, d2, d3;
                ldsm_x4(d0, d1, d2, d3,
                        bbase + (unsigned)(ntp * 16 * GST + kb * 16) * 2);
                bf[ntp * 2 + 0][0] = d0; bf[ntp * 2 + 0][1] = d1;
                bf[ntp * 2 + 1][0] = d2; bf[ntp * 2 + 1][1] = d3;
            }
            #pragma unroll
            for (int mt = 0; mt < 4; mt++)
                #pragma unroll
                for (int nt = 0; nt < 4; nt++)
                    mma_f16(acc[mt][nt], af[mt][0], af[mt][1], af[mt][2], af[mt][3],
                            bf[nt][0], bf[nt][1]);
        }
        __syncthreads();                 // done reading buf s before s+2 writes it
    }
    #undef ISSUE

    // epilogue
    #pragma unroll
    for (int mt = 0; mt < 4; mt++) {
        #pragma unroll
        for (int nt = 0; nt < 4; nt++) {
            int r0 = rowBase + wm * 64 + mt * 16 + g;
            int c  = colBase + wn * 32 + nt * 8 + 2 * t4;
            float bx = bias[c], by = bias[c + 1];
            if (HALF_OUT) {
                __half* out = (__half*)Cout;
                *(unsigned*)(out + (size_t)r0 * N + c) =
                    f2h2(acc[mt][nt][0] + bx, acc[mt][nt][1] + by);
                *(unsigned*)(out + (size_t)(r0 + 8) * N + c) =
                    f2h2(acc[mt][nt][2] + bx, acc[mt][nt][3] + by);
            } else {
                float* out = (float*)Cout;
                *(float2*)(out + (size_t)r0 * N + c) =
                    make_float2(acc[mt][nt][0] + bx, acc[mt][nt][1] + by);
                *(float2*)(out + (size_t)(r0 + 8) * N + c) =
                    make_float2(acc[mt][nt][2] + bx, acc[mt][nt][3] + by);
            }
        }
    }
}

// ---------------------------------------------------------------------------
// Flash causal attention (R6 structure), fp16 in/out.
// ---------------------------------------------------------------------------
#define QST2 72
#define KST2 72
#define VST2 72
#define PST2 40

__global__ __launch_bounds__(128) void attn_f16(
    const __half* __restrict__ qkv, __half* __restrict__ outp)
{
    __shared__ __align__(16) __half Qs[64 * QST2];
    __shared__ __align__(16) __half Ks[32 * KST2];
    __shared__ __align__(16) __half Vs[32 * VST2];
    __shared__ __align__(16) __half Ps[64 * PST2];

    const int tid  = threadIdx.x;
    const int lane = tid & 31;
    const int wid  = tid >> 5;
    const int g    = lane >> 2;
    const int t4   = lane & 3;

    const int bh = blockIdx.y;
    const int b  = bh / H_;
    const int h  = bh % H_;
    const int qt = blockIdx.x;
    const int qBase = qt * 64;

    const __half* qptr = qkv + (size_t)b * T_ * C3_ + h * D_;
    const __half* kptr = qptr + C_;
    const __half* vptr = qptr + 2 * C_;

    const unsigned qoff = ((lane & 7) + ((lane >> 3) & 1) * 8) * QST2
                        + ((lane >> 4) & 1) * 8;
    const unsigned koff = ((lane & 7) + ((lane >> 4) & 1) * 8) * KST2
                        + ((lane >> 3) & 1) * 8;
    const unsigned voff = ((lane & 7) + ((lane >> 3) & 1) * 8) * VST2
                        + ((lane >> 4) & 1) * 8;
    const unsigned poff = ((lane & 7) + ((lane >> 3) & 1) * 8) * PST2
                        + ((lane >> 4) & 1) * 8;
    const unsigned Qs_base = s2u(&Qs[0]);
    const unsigned Ks_base = s2u(&Ks[0]);
    const unsigned Vs_base = s2u(&Vs[0]);
    const unsigned Ps_base = s2u(&Ps[0]);

    // stage Q tile (fp16 direct)
    #pragma unroll
    for (int l = 0; l < 4; l++) {
        int idx = tid + l * 128;
        int r = idx >> 3, c8 = (idx & 7) << 3;
        *(uint4*)&Qs[r * QST2 + c8] =
            *(const uint4*)(qptr + (size_t)(qBase + r) * C3_ + c8);
    }
    __syncthreads();

    unsigned qa[4][4];
    #pragma unroll
    for (int kq = 0; kq < 4; kq++)
        ldsm_x4(qa[kq][0], qa[kq][1], qa[kq][2], qa[kq][3],
                Qs_base + (qoff + (unsigned)(wid * 16 * QST2 + kq * 16)) * 2);

    float o[8][4];
    #pragma unroll
    for (int nt = 0; nt < 8; nt++)
        #pragma unroll
        for (int q = 0; q < 4; q++) o[nt][q] = 0.f;
    float m0 = -1e30f, m1 = -1e30f, l0 = 0.f, l1 = 0.f;

    const float scale = 0.125f;
    const int rowL = wid * 16 + g;
    const int row0 = qBase + rowL;
    const int row1 = row0 + 8;

    const int ktmax = 2 * qt + 1;
    for (int kt = 0; kt <= ktmax; kt++) {
        const int kBase = kt * 32;
        const bool domask = (kt >= 2 * qt);

        __syncthreads();
        #pragma unroll
        for (int l = 0; l < 2; l++) {
            int idx = tid + l * 128;
            int r = idx >> 3, c8 = (idx & 7) << 3;
            *(uint4*)&Ks[r * KST2 + c8] =
                *(const uint4*)(kptr + (size_t)(kBase + r) * C3_ + c8);
            *(uint4*)&Vs[r * VST2 + c8] =
                *(const uint4*)(vptr + (size_t)(kBase + r) * C3_ + c8);
        }
        __syncthreads();

        float s[4][4];
        #pragma unroll
        for (int nt = 0; nt < 4; nt++)
            #pragma unroll
            for (int q = 0; q < 4; q++) s[nt][q] = 0.f;

        #pragma unroll
        for (int kq = 0; kq < 4; kq++) {
            #pragma unroll
            for (int ntp = 0; ntp < 2; ntp++) {
                unsigned d0, d1, d2, d3;
                ldsm_x4(d0, d1, d2, d3,
                        Ks_base + (koff + (unsigned)(ntp * 16 * KST2 + kq * 16)) * 2);
                mma_f16(s[ntp * 2 + 0], qa[kq][0], qa[kq][1], qa[kq][2], qa[kq][3],
                        d0, d1);
                mma_f16(s[ntp * 2 + 1], qa[kq][0], qa[kq][1], qa[kq][2], qa[kq][3],
                        d2, d3);
            }
        }

        #pragma unroll
        for (int nt = 0; nt < 4; nt++) {
            #pragma unroll
            for (int q = 0; q < 4; q++) {
                s[nt][q] *= scale;
                if (domask) {
                    int col = kBase + nt * 8 + 2 * t4 + (q & 1);
                    int row = (q < 2) ? row0 : row1;
                    if (col > row) s[nt][q] = -1e30f;
                }
            }
        }

        float mt0 = -1e30f, mt1 = -1e30f;
        #pragma unroll
        for (int nt = 0; nt < 4; nt++) {
            mt0 = fmaxf(mt0, fmaxf(s[nt][0], s[nt][1]));
            mt1 = fmaxf(mt1, fmaxf(s[nt][2], s[nt][3]));
        }
        mt0 = fmaxf(mt0, __shfl_xor_sync(0xffffffffu, mt0, 1));
        mt0 = fmaxf(mt0, __shfl_xor_sync(0xffffffffu, mt0, 2));
        mt1 = fmaxf(mt1, __shfl_xor_sync(0xffffffffu, mt1, 1));
        mt1 = fmaxf(mt1, __shfl_xor_sync(0xffffffffu, mt1, 2));

        float mn0 = fmaxf(m0, mt0), mn1 = fmaxf(m1, mt1);
        float al0 = __expf(m0 - mn0), al1 = __expf(m1 - mn1);
        m0 = mn0; m1 = mn1;

        float rs0 = 0.f, rs1 = 0.f;
        #pragma unroll
        for (int nt = 0; nt < 4; nt++) {
            s[nt][0] = __expf(s[nt][0] - mn0);
            s[nt][1] = __expf(s[nt][1] - mn0);
            s[nt][2] = __expf(s[nt][2] - mn1);
            s[nt][3] = __expf(s[nt][3] - mn1);
            rs0 += s[nt][0] + s[nt][1];
            rs1 += s[nt][2] + s[nt][3];
        }
        rs0 += __shfl_xor_sync(0xffffffffu, rs0, 1);
        rs0 += __shfl_xor_sync(0xffffffffu, rs0, 2);
        rs1 += __shfl_xor_sync(0xffffffffu, rs1, 1);
        rs1 += __shfl_xor_sync(0xffffffffu, rs1, 2);
        l0 = l0 * al0 + rs0;
        l1 = l1 * al1 + rs1;

        #pragma unroll
        for (int nt = 0; nt < 8; nt++) {
            o[nt][0] *= al0; o[nt][1] *= al0;
            o[nt][2] *= al1; o[nt][3] *= al1;
        }

        #pragma unroll
        for (int nt = 0; nt < 4; nt++) {
            int c = nt * 8 + 2 * t4;
            *(unsigned*)&Ps[(rowL    ) * PST2 + c] = f2h2(s[nt][0], s[nt][1]);
            *(unsigned*)&Ps[(rowL + 8) * PST2 + c] = f2h2(s[nt][2], s[nt][3]);
        }
        __syncwarp();

        #pragma unroll
        for (int kb = 0; kb < 2; kb++) {
            unsigned a0, a1, a2, a3;
            ldsm_x4(a0, a1, a2, a3,
                    Ps_base + (poff + (unsigned)(wid * 16 * PST2 + kb * 16)) * 2);
            #pragma unroll
            for (int ntp = 0; ntp < 4; ntp++) {
                unsigned d0, d1, d2, d3;
                ldsm_x4_t(d0, d1, d2, d3,
                          Vs_base + (voff + (unsigned)(kb * 16 * VST2 + ntp * 16)) * 2);
                mma_f16(o[ntp * 2 + 0], a0, a1, a2, a3, d0, d1);
                mma_f16(o[ntp * 2 + 1], a0, a1, a2, a3, d2, d3);
            }
        }
    }

    // epilogue (fp16 out)
    float inv0 = 1.f / l0, inv1 = 1.f / l1;
    #pragma unroll
    for (int nt = 0; nt < 8; nt++) {
        int d = nt * 8 + 2 * t4;
        unsigned u0 = f2h2(o[nt][0] * inv0, o[nt][1] * inv0);
        unsigned u1 = f2h2(o[nt][2] * inv1, o[nt][3] * inv1);
        *(unsigned*)(outp + ((size_t)b * T_ + row0) * C_ + h * D_ + d) = u0;
        *(unsigned*)(outp + ((size_t)b * T_ + row1) * C_ + h * D_ + d) = u1;
    }
}

// ---------------------------------------------------------------------------
extern "C" void kernel_launch(void* const* d_in, const int* in_sizes, int n_in,
                              void* d_out, int out_size)
{
    (void)in_sizes; (void)n_in; (void)out_size;
    const float* x      = (const float*)d_in[0];
    const float* w_attn = (const float*)d_in[1];
    const float* b_attn = (const float*)d_in[2];
    const float* w_proj = (const float*)d_in[3];
    const float* b_proj = (const float*)d_in[4];
    float* out = (float*)d_out;

    __half *qkv_h, *att_h, *xh, *waT, *wpT;
    cudaGetSymbolAddress((void**)&qkv_h, g_qkv_h);
    cudaGetSymbolAddress((void**)&att_h, g_att_h);
    cudaGetSymbolAddress((void**)&xh,    g_xh);
    cudaGetSymbolAddress((void**)&waT,   g_waT);
    cudaGetSymbolAddress((void**)&wpT,   g_wpT);

    // prep: x -> fp16 ; weights -> transposed fp16 [N][K]
    const int n4 = MT_ * C_ / 4;
    cvt_x_kernel<<<(n4 + 255) / 256, 256>>>(x, xh, n4);
    transpose_cvt_kernel<<<dim3(C3_ / 32, C_ / 32), 256>>>(w_attn, waT, C_, C3_);
    transpose_cvt_kernel<<<dim3(C_ / 32, C_ / 32), 256>>>(w_proj, wpT, C_, C_);

    // QKV: [8192,768] @ [768,2304] -> fp16
    gemm_f16ca<true><<<dim3(C3_ / 128, MT_ / 128), 256>>>(
        xh, waT, b_attn, qkv_h, MT_, C3_, C_);

    // attention (fp16 in/out)
    attn_f16<<<dim3(T_ / 64, B_ * H_), 128>>>(qkv_h, att_h);

    // proj: [8192,768] @ [768,768] -> fp32 + bias
    gemm_f16ca<false><<<dim3(C_ / 128, MT_ / 128), 256>>>(
        att_h, wpT, b_proj, out, MT_, C_, C_);
}

// round 9
// speedup vs baseline: 3.0576x; 1.0932x over previous
#include <cuda_runtime.h>
#include <cuda_fp16.h>
#include <cstdint>

#define B_   8
#define T_   1024
#define C_   768
#define H_   12
#define D_   64
#define C3_  2304
#define MT_  (B_ * T_)      // 8192 rows

__device__ __half g_qkv_h[(size_t)MT_ * C3_];  // [t][3C]
__device__ __half g_att_h[(size_t)MT_ * C_];   // [t][C]
__device__ __half g_xh  [(size_t)MT_ * C_];    // x as fp16
__device__ __half g_waT [(size_t)C3_ * C_];    // w_attn^T  [N][K]
__device__ __half g_wpT [(size_t)C_  * C_];    // w_proj^T  [N][K]

// ---------------------------------------------------------------------------
__device__ __forceinline__ unsigned f2h2(float x, float y) {
    __half2 h = __floats2half2_rn(x, y);
    return *reinterpret_cast<unsigned*>(&h);
}
__device__ __forceinline__ uint32_t s2u(const void* p) {
    return (uint32_t)__cvta_generic_to_shared(p);
}
__device__ __forceinline__ void mma_f16(float c[4],
    unsigned a0, unsigned a1, unsigned a2, unsigned a3,
    unsigned b0, unsigned b1)
{
    asm volatile(
        "mma.sync.aligned.m16n8k16.row.col.f32.f16.f16.f32 "
        "{%0,%1,%2,%3}, {%4,%5,%6,%7}, {%8,%9}, {%0,%1,%2,%3};\n"
        : "+f"(c[0]), "+f"(c[1]), "+f"(c[2]), "+f"(c[3])
        : "r"(a0), "r"(a1), "r"(a2), "r"(a3), "r"(b0), "r"(b1));
}
__device__ __forceinline__ void ldsm_x4(unsigned& d0, unsigned& d1,
                                        unsigned& d2, unsigned& d3, unsigned saddr)
{
    asm volatile("ldmatrix.sync.aligned.m8n8.x4.shared.b16 {%0,%1,%2,%3}, [%4];\n"
                 : "=r"(d0), "=r"(d1), "=r"(d2), "=r"(d3) : "r"(saddr));
}
__device__ __forceinline__ void ldsm_x4_t(unsigned& d0, unsigned& d1,
                                          unsigned& d2, unsigned& d3, unsigned saddr)
{
    asm volatile("ldmatrix.sync.aligned.m8n8.x4.trans.shared.b16 {%0,%1,%2,%3}, [%4];\n"
                 : "=r"(d0), "=r"(d1), "=r"(d2), "=r"(d3) : "r"(saddr));
}
__device__ __forceinline__ void cp16(uint32_t saddr, const void* gaddr) {
    asm volatile("cp.async.cg.shared.global [%0], [%1], 16;"
                 :: "r"(saddr), "l"(gaddr));
}
#define CP_COMMIT()  asm volatile("cp.async.commit_group;" ::: "memory")
#define CP_WAIT0()   asm volatile("cp.async.wait_group 0;" ::: "memory")
#define CP_WAIT1()   asm volatile("cp.async.wait_group 1;" ::: "memory")

// ---------------------------------------------------------------------------
// prep kernels
// ---------------------------------------------------------------------------
__global__ void cvt_x_kernel(const float* __restrict__ x, __half* __restrict__ xh,
                             int n4) {
    int i = blockIdx.x * blockDim.x + threadIdx.x;
    if (i < n4) {
        float4 v = ((const float4*)x)[i];
        uint2 h;
        h.x = f2h2(v.x, v.y);
        h.y = f2h2(v.z, v.w);
        ((uint2*)xh)[i] = h;
    }
}

__global__ __launch_bounds__(256) void transpose_cvt_kernel(
    const float* __restrict__ w, __half* __restrict__ wt, int K, int N)
{
    __shared__ float tile[32][33];
    int n0 = blockIdx.x * 32, k0 = blockIdx.y * 32;
    int tx = threadIdx.x & 31, ty = threadIdx.x >> 5;
    #pragma unroll
    for (int i = ty; i < 32; i += 8)
        tile[i][tx] = w[(size_t)(k0 + i) * N + n0 + tx];
    __syncthreads();
    #pragma unroll
    for (int i = ty; i < 32; i += 8)
        wt[(size_t)(n0 + i) * K + k0 + tx] = __float2half(tile[tx][i]);
}

// ---------------------------------------------------------------------------
// FP16 GEMM, 3-stage cp.async pipeline, swizzled smem (64B rows, no padding).
// Cout[M,N] = A[M,K] @ Bt[N,K]^T + bias.  128x128 tile, BK=32,
// 256 thr = 8 warps (2m x 4n), warp 64x32. One __syncthreads per stage.
// smem layout: byte = row*64 + ((chunk ^ ((row>>1)&3))<<4), chunk = k16B-idx.
// ---------------------------------------------------------------------------
template<bool HALF_OUT>
__global__ __launch_bounds__(256) void gemm_f16s(
    const __half* __restrict__ A, const __half* __restrict__ Bt,
    const float* __restrict__ bias, void* __restrict__ Cout,
    int M, int N, int K)
{
    __shared__ __align__(128) __half As[3][128 * 32];
    __shared__ __align__(128) __half Bs[3][128 * 32];
    const unsigned BUFB = 8192;

    const int tid  = threadIdx.x;
    const int lane = tid & 31;
    const int wid  = tid >> 5;
    const int wm   = wid >> 2;
    const int wn   = wid & 3;
    const int g    = lane >> 2;
    const int t4   = lane & 3;

    const int rowBase = blockIdx.y * 128;
    const int colBase = blockIdx.x * 128;

    // per-lane swizzled fragment offsets (bytes)
    const int l7   = lane & 7;
    const int lb8  = (lane >> 3) & 1;
    const int lb16 = (lane >> 4) & 1;
    const int xor3 = (l7 >> 1) & 3;
    const unsigned aoffL = (unsigned)((l7 + 8 * lb8) * 64
                         + (((lb16 ^ (xor3 & 1)) | (xor3 & 2)) << 4));
    const unsigned boffL = (unsigned)((l7 + 8 * lb16) * 64
                         + (((lb8  ^ (xor3 & 1)) | (xor3 & 2)) << 4));

    const unsigned As_base = s2u(&As[0][0]);
    const unsigned Bs_base = s2u(&Bs[0][0]);

    float acc[4][4][4];
    #pragma unroll
    for (int i = 0; i < 4; i++)
        #pragma unroll
        for (int j = 0; j < 4; j++)
            #pragma unroll
            for (int q = 0; q < 4; q++) acc[i][j][q] = 0.f;

    // loader: thread -> row tid>>1, chunks {2(tid&1), 2(tid&1)+1}
    const int ldR = tid >> 1;
    const int c0  = 2 * (tid & 1);
    const unsigned sOff = (unsigned)(ldR * 64 + ((c0 ^ ((ldR >> 1) & 3)) << 4));
    const __half* gA = A  + (size_t)(rowBase + ldR) * K + (tid & 1) * 16;
    const __half* gB = Bt + (size_t)(colBase + ldR) * K + (tid & 1) * 16;

    #define ISSUE(s, wb) {                                        \
        const unsigned bo = (unsigned)(wb) * BUFB;                \
        const __half* ga = gA + (size_t)(s) * 32;                 \
        const __half* gb = gB + (size_t)(s) * 32;                 \
        cp16(As_base + bo + sOff,         ga);                    \
        cp16((As_base + bo + sOff) ^ 16u, ga + 8);                \
        cp16(Bs_base + bo + sOff,         gb);                    \
        cp16((Bs_base + bo + sOff) ^ 16u, gb + 8);                \
        CP_COMMIT();                                              \
    }

    const int NS = K / 32;     // >= 2 always here
    ISSUE(0, 0);
    ISSUE(1, 1);
    int wbuf = 2, rbuf = 0;

    for (int s = 0; s < NS; s++) {
        if (s + 1 < NS) CP_WAIT1(); else CP_WAIT0();
        __syncthreads();                       // stage s visible; stage s-1 free
        if (s + 2 < NS) {
            ISSUE(s + 2, wbuf);
            wbuf = (wbuf == 2) ? 0 : wbuf + 1;
        }

        const unsigned aw = As_base + (unsigned)rbuf * BUFB
                          + (unsigned)(wm * 4096) + aoffL;
        const unsigned bw = Bs_base + (unsigned)rbuf * BUFB
                          + (unsigned)(wn * 2048) + boffL;
        #pragma unroll
        for (int kb = 0; kb < 2; kb++) {
            unsigned af[4][4];
            #pragma unroll
            for (int mt = 0; mt < 4; mt++)
                ldsm_x4(af[mt][0], af[mt][1], af[mt][2], af[mt][3],
                        (aw + (unsigned)(mt * 1024)) ^ (unsigned)(kb << 5));
            unsigned bf[4][2];
            #pragma unroll
            for (int ntp = 0; ntp < 2; ntp++) {
                unsigned d0, d1, d2, d3;
                ldsm_x4(d0, d1, d2, d3,
                        (bw + (unsigned)(ntp * 1024)) ^ (unsigned)(kb << 5));
                bf[ntp * 2 + 0][0] = d0; bf[ntp * 2 + 0][1] = d1;
                bf[ntp * 2 + 1][0] = d2; bf[ntp * 2 + 1][1] = d3;
            }
            #pragma unroll
            for (int mt = 0; mt < 4; mt++)
                #pragma unroll
                for (int nt = 0; nt < 4; nt++)
                    mma_f16(acc[mt][nt], af[mt][0], af[mt][1], af[mt][2], af[mt][3],
                            bf[nt][0], bf[nt][1]);
        }
        rbuf = (rbuf == 2) ? 0 : rbuf + 1;
    }
    #undef ISSUE

    // epilogue
    #pragma unroll
    for (int mt = 0; mt < 4; mt++) {
        #pragma unroll
        for (int nt = 0; nt < 4; nt++) {
            int r0 = rowBase + wm * 64 + mt * 16 + g;
            int c  = colBase + wn * 32 + nt * 8 + 2 * t4;
            float bx = bias[c], by = bias[c + 1];
            if (HALF_OUT) {
                __half* out = (__half*)Cout;
                *(unsigned*)(out + (size_t)r0 * N + c) =
                    f2h2(acc[mt][nt][0] + bx, acc[mt][nt][1] + by);
                *(unsigned*)(out + (size_t)(r0 + 8) * N + c) =
                    f2h2(acc[mt][nt][2] + bx, acc[mt][nt][3] + by);
            } else {
                float* out = (float*)Cout;
                *(float2*)(out + (size_t)r0 * N + c) =
                    make_float2(acc[mt][nt][0] + bx, acc[mt][nt][1] + by);
                *(float2*)(out + (size_t)(r0 + 8) * N + c) =
                    make_float2(acc[mt][nt][2] + bx, acc[mt][nt][3] + by);
            }
        }
    }
}

// ---------------------------------------------------------------------------
// Flash causal attention, fp16, cp.async double-buffered K/V, 1 sync per tile.
// 128 threads = 4 warps, 64 q-rows/block, 32-key tiles.
// ---------------------------------------------------------------------------
#define QST2 72
#define KST2 72
#define PST2 40

__global__ __launch_bounds__(128) void attn_f16(
    const __half* __restrict__ qkv, __half* __restrict__ outp)
{
    __shared__ __align__(16) __half Qs[64 * QST2];
    __shared__ __align__(16) __half Ks[2][32 * KST2];
    __shared__ __align__(16) __half Vs[2][32 * KST2];
    __shared__ __align__(16) __half Ps[64 * PST2];
    const unsigned KVB = 32 * KST2 * 2;   // bytes per buffer

    const int tid  = threadIdx.x;
    const int lane = tid & 31;
    const int wid  = tid >> 5;
    const int g    = lane >> 2;
    const int t4   = lane & 3;

    const int bh = blockIdx.y;
    const int b  = bh / H_;
    const int h  = bh % H_;
    const int qt = blockIdx.x;
    const int qBase = qt * 64;

    const __half* qptr = qkv + (size_t)b * T_ * C3_ + h * D_;
    const __half* kptr = qptr + C_;
    const __half* vptr = qptr + 2 * C_;

    const unsigned qoff = ((lane & 7) + ((lane >> 3) & 1) * 8) * QST2
                        + ((lane >> 4) & 1) * 8;
    const unsigned koff = ((lane & 7) + ((lane >> 4) & 1) * 8) * KST2
                        + ((lane >> 3) & 1) * 8;
    const unsigned voff = ((lane & 7) + ((lane >> 3) & 1) * 8) * KST2
                        + ((lane >> 4) & 1) * 8;
    const unsigned poff = ((lane & 7) + ((lane >> 3) & 1) * 8) * PST2
                        + ((lane >> 4) & 1) * 8;
    const unsigned Qs_base = s2u(&Qs[0]);
    const unsigned Ks_base = s2u(&Ks[0][0]);
    const unsigned Vs_base = s2u(&Vs[0][0]);
    const unsigned Ps_base = s2u(&Ps[0]);

    // loader roles for K/V tiles (2 x 16B chunks each per tile)
    const int r0l = tid >> 3;                 // rows tid>>3 and +16
    const int c8l = (tid & 7) << 3;
    const unsigned sK0 = Ks_base + (unsigned)(r0l * KST2 + c8l) * 2;
    const unsigned sK1 = Ks_base + (unsigned)((r0l + 16) * KST2 + c8l) * 2;
    const unsigned sV0 = Vs_base + (unsigned)(r0l * KST2 + c8l) * 2;
    const unsigned sV1 = Vs_base + (unsigned)((r0l + 16) * KST2 + c8l) * 2;

    #define AISSUE(kt, wb) {                                                  \
        const unsigned bo = (unsigned)(wb) * KVB;                             \
        const __half* gk0 = kptr + (size_t)((kt) * 32 + r0l) * C3_ + c8l;     \
        const __half* gv0 = vptr + (size_t)((kt) * 32 + r0l) * C3_ + c8l;     \
        cp16(sK0 + bo, gk0);                                                  \
        cp16(sK1 + bo, gk0 + 16 * C3_);                                       \
        cp16(sV0 + bo, gv0);                                                  \
        cp16(sV1 + bo, gv0 + 16 * C3_);                                       \
        CP_COMMIT();                                                          \
    }

    // stage Q tile (fp16 direct)
    #pragma unroll
    for (int l = 0; l < 4; l++) {
        int idx = tid + l * 128;
        int r = idx >> 3, c8 = (idx & 7) << 3;
        *(uint4*)&Qs[r * QST2 + c8] =
            *(const uint4*)(qptr + (size_t)(qBase + r) * C3_ + c8);
    }
    AISSUE(0, 0);
    __syncthreads();

    unsigned qa[4][4];
    #pragma unroll
    for (int kq = 0; kq < 4; kq++)
        ldsm_x4(qa[kq][0], qa[kq][1], qa[kq][2], qa[kq][3],
                Qs_base + (qoff + (unsigned)(wid * 16 * QST2 + kq * 16)) * 2);

    float o[8][4];
    #pragma unroll
    for (int nt = 0; nt < 8; nt++)
        #pragma unroll
        for (int q = 0; q < 4; q++) o[nt][q] = 0.f;
    float m0 = -1e30f, m1 = -1e30f, l0 = 0.f, l1 = 0.f;

    const float scale = 0.125f;
    const int rowL = wid * 16 + g;
    const int row0 = qBase + rowL;
    const int row1 = row0 + 8;

    const int ktmax = 2 * qt + 1;
    for (int kt = 0; kt <= ktmax; kt++) {
        const int kBase = kt * 32;
        const bool domask = (kt >= 2 * qt);
        const unsigned rb = (unsigned)(kt & 1) * KVB;

        CP_WAIT0();
        __syncthreads();                 // tile kt ready; tile kt-1 consumers done
        if (kt + 1 <= ktmax) AISSUE(kt + 1, (kt + 1) & 1);

        // S = Q @ K^T
        float s[4][4];
        #pragma unroll
        for (int nt = 0; nt < 4; nt++)
            #pragma unroll
            for (int q = 0; q < 4; q++) s[nt][q] = 0.f;

        #pragma unroll
        for (int kq = 0; kq < 4; kq++) {
            #pragma unroll
            for (int ntp = 0; ntp < 2; ntp++) {
                unsigned d0, d1, d2, d3;
                ldsm_x4(d0, d1, d2, d3,
                        Ks_base + rb + (koff + (unsigned)(ntp * 16 * KST2 + kq * 16)) * 2);
                mma_f16(s[ntp * 2 + 0], qa[kq][0], qa[kq][1], qa[kq][2], qa[kq][3],
                        d0, d1);
                mma_f16(s[ntp * 2 + 1], qa[kq][0], qa[kq][1], qa[kq][2], qa[kq][3],
                        d2, d3);
            }
        }

        #pragma unroll
        for (int nt = 0; nt < 4; nt++) {
            #pragma unroll
            for (int q = 0; q < 4; q++) {
                s[nt][q] *= scale;
                if (domask) {
                    int col = kBase + nt * 8 + 2 * t4 + (q & 1);
                    int row = (q < 2) ? row0 : row1;
                    if (col > row) s[nt][q] = -1e30f;
                }
            }
        }

        float mt0 = -1e30f, mt1 = -1e30f;
        #pragma unroll
        for (int nt = 0; nt < 4; nt++) {
            mt0 = fmaxf(mt0, fmaxf(s[nt][0], s[nt][1]));
            mt1 = fmaxf(mt1, fmaxf(s[nt][2], s[nt][3]));
        }
        mt0 = fmaxf(mt0, __shfl_xor_sync(0xffffffffu, mt0, 1));
        mt0 = fmaxf(mt0, __shfl_xor_sync(0xffffffffu, mt0, 2));
        mt1 = fmaxf(mt1, __shfl_xor_sync(0xffffffffu, mt1, 1));
        mt1 = fmaxf(mt1, __shfl_xor_sync(0xffffffffu, mt1, 2));

        float mn0 = fmaxf(m0, mt0), mn1 = fmaxf(m1, mt1);
        float al0 = __expf(m0 - mn0), al1 = __expf(m1 - mn1);
        m0 = mn0; m1 = mn1;

        float rs0 = 0.f, rs1 = 0.f;
        #pragma unroll
        for (int nt = 0; nt < 4; nt++) {
            s[nt][0] = __expf(s[nt][0] - mn0);
            s[nt][1] = __expf(s[nt][1] - mn0);
            s[nt][2] = __expf(s[nt][2] - mn1);
            s[nt][3] = __expf(s[nt][3] - mn1);
            rs0 += s[nt][0] + s[nt][1];
            rs1 += s[nt][2] + s[nt][3];
        }
        rs0 += __shfl_xor_sync(0xffffffffu, rs0, 1);
        rs0 += __shfl_xor_sync(0xffffffffu, rs0, 2);
        rs1 += __shfl_xor_sync(0xffffffffu, rs1, 1);
        rs1 += __shfl_xor_sync(0xffffffffu, rs1, 2);
        l0 = l0 * al0 + rs0;
        l1 = l1 * al1 + rs1;

        #pragma unroll
        for (int nt = 0; nt < 8; nt++) {
            o[nt][0] *= al0; o[nt][1] *= al0;
            o[nt][2] *= al1; o[nt][3] *= al1;
        }

        #pragma unroll
        for (int nt = 0; nt < 4; nt++) {
            int c = nt * 8 + 2 * t4;
            *(unsigned*)&Ps[(rowL    ) * PST2 + c] = f2h2(s[nt][0], s[nt][1]);
            *(unsigned*)&Ps[(rowL + 8) * PST2 + c] = f2h2(s[nt][2], s[nt][3]);
        }
        __syncwarp();

        #pragma unroll
        for (int kb = 0; kb < 2; kb++) {
            unsigned a0, a1, a2, a3;
            ldsm_x4(a0, a1, a2, a3,
                    Ps_base + (poff + (unsigned)(wid * 16 * PST2 + kb * 16)) * 2);
            #pragma unroll
            for (int ntp = 0; ntp < 4; ntp++) {
                unsigned d0, d1, d2, d3;
                ldsm_x4_t(d0, d1, d2, d3,
                          Vs_base + rb + (voff + (unsigned)(kb * 16 * KST2 + ntp * 16)) * 2);
                mma_f16(o[ntp * 2 + 0], a0, a1, a2, a3, d0, d1);
                mma_f16(o[ntp * 2 + 1], a0, a1, a2, a3, d2, d3);
            }
        }
    }
    #undef AISSUE

    // epilogue (fp16 out)
    float inv0 = 1.f / l0, inv1 = 1.f / l1;
    #pragma unroll
    for (int nt = 0; nt < 8; nt++) {
        int d = nt * 8 + 2 * t4;
        unsigned u0 = f2h2(o[nt][0] * inv0, o[nt][1] * inv0);
        unsigned u1 = f2h2(o[nt][2] * inv1, o[nt][3] * inv1);
        *(unsigned*)(outp + ((size_t)b * T_ + row0) * C_ + h * D_ + d) = u0;
        *(unsigned*)(outp + ((size_t)b * T_ + row1) * C_ + h * D_ + d) = u1;
    }
}

// ---------------------------------------------------------------------------
extern "C" void kernel_launch(void* const* d_in, const int* in_sizes, int n_in,
                              void* d_out, int out_size)
{
    (void)in_sizes; (void)n_in; (void)out_size;
    const float* x      = (const float*)d_in[0];
    const float* w_attn = (const float*)d_in[1];
    const float* b_attn = (const float*)d_in[2];
    const float* w_proj = (const float*)d_in[3];
    const float* b_proj = (const float*)d_in[4];
    float* out = (float*)d_out;

    __half *qkv_h, *att_h, *xh, *waT, *wpT;
    cudaGetSymbolAddress((void**)&qkv_h, g_qkv_h);
    cudaGetSymbolAddress((void**)&att_h, g_att_h);
    cudaGetSymbolAddress((void**)&xh,    g_xh);
    cudaGetSymbolAddress((void**)&waT,   g_waT);
    cudaGetSymbolAddress((void**)&wpT,   g_wpT);

    const int n4 = MT_ * C_ / 4;
    cvt_x_kernel<<<(n4 + 255) / 256, 256>>>(x, xh, n4);
    transpose_cvt_kernel<<<dim3(C3_ / 32, C_ / 32), 256>>>(w_attn, waT, C_, C3_);
    transpose_cvt_kernel<<<dim3(C_ / 32, C_ / 32), 256>>>(w_proj, wpT, C_, C_);

    gemm_f16s<true><<<dim3(C3_ / 128, MT_ / 128), 256>>>(
        xh, waT, b_attn, qkv_h, MT_, C3_, C_);

    attn_f16<<<dim3(T_ / 64, B_ * H_), 128>>>(qkv_h, att_h);

    gemm_f16s<false><<<dim3(C_ / 128, MT_ / 128), 256>>>(
        att_h, wpT, b_proj, out, MT_, C_, C_);
}